// round 7
// baseline (speedup 1.0000x reference)
#include <cuda_runtime.h>
#include <math.h>

// Problem dims
#define Bb   64
#define Tt   512
#define Dd   256
#define Hh   1024
#define Gg   4096          // 4*H
#define Mm   32768         // B*T
#define NCTA 128

// ---------------- scratch (__device__ globals; no dynamic allocation) ----------
__device__ float d_xg[(size_t)Tt * Gg * Bb];      // [t][m=j*4+g][b]   512 MB
__device__ float d_Af[(size_t)Gg * Hh];           // Wh tf32 A-fragments, 16 MB
__device__ float d_Axf[(size_t)Gg * Dd];          // Wx tf32 A-fragments, 4 MB
__device__ float d_Wof[(size_t)Dd * Hh];          // Wout tf32 A-fragments, 1 MB
__device__ float d_hsJ[(size_t)Hh * Mm];          // [j][m'] , m'=t*64+b   128 MB
__device__ float d_outT[(size_t)Dd * Mm];         // out head, [d][m']     32 MB
__device__ float d_h2[2 * Hh * Bb];               // double-buffered h, [buf][k][b]
__device__ unsigned d_bcount;
__device__ unsigned d_bgen;

__device__ __forceinline__ unsigned tf32r(float x)
{
    unsigned u;
    asm("cvt.rna.tf32.f32 %0, %1;" : "=r"(u) : "f"(x));
    return u;
}

// tf32 mma: D(m16n8) += A(m16k8) * B(k8n8)
#define MMA_TF32(d, a0, a1, a2, a3, b0, b1)                                     \
    asm volatile("mma.sync.aligned.m16n8k8.row.col.f32.tf32.tf32.f32 "          \
                 "{%0,%1,%2,%3}, {%4,%5,%6,%7}, {%8,%9}, {%0,%1,%2,%3};"        \
                 : "+f"(d[0]), "+f"(d[1]), "+f"(d[2]), "+f"(d[3])               \
                 : "r"(a0), "r"(a1), "r"(a2), "r"(a3), "r"(b0), "r"(b1))

// ---------------- init: zero h state, reset barrier ----------------------------
__global__ void init_k()
{
    int i = blockIdx.x * blockDim.x + threadIdx.x;
    if (i < 2 * Hh * Bb) d_h2[i] = 0.0f;
    if (i == 0) { d_bcount = 0u; d_bgen = 0u; }
}

// ---------------- combined weight-fragment packing ------------------------------
// blocks [0,4096): Wh frags   [4096,5120): Wx frags   [5120,5376): Wout frags
__global__ void pack_all(const float* __restrict__ Wh, const float* __restrict__ Wx,
                         const float* __restrict__ Wo)
{
    int blk = blockIdx.x;
    if (blk < 4096) {
        size_t i = (size_t)blk * 256 + threadIdx.x;
        int lane = i & 31;
        int kc   = (i >> 5) & 127;
        int ms   = (i >> 12) & 1;
        int cb   = (int)(i >> 13);
        int g = lane >> 2, tig = lane & 3;
        int m1 = ms * 16 + g, m2 = m1 + 8;
        int r1 = (m1 & 3) * Hh + cb * 8 + (m1 >> 2);
        int r2 = (m2 & 3) * Hh + cb * 8 + (m2 >> 2);
        int k0 = kc * 8;
        float4 v;
        v.x = __uint_as_float(tf32r(Wh[(size_t)r1 * Hh + k0 + tig]));
        v.y = __uint_as_float(tf32r(Wh[(size_t)r2 * Hh + k0 + tig]));
        v.z = __uint_as_float(tf32r(Wh[(size_t)r1 * Hh + k0 + tig + 4]));
        v.w = __uint_as_float(tf32r(Wh[(size_t)r2 * Hh + k0 + tig + 4]));
        ((float4*)d_Af)[i] = v;
    } else if (blk < 5120) {
        size_t i = (size_t)(blk - 4096) * 256 + threadIdx.x;
        int lane = i & 31;
        int k8   = (i >> 5) & 31;
        int ws   = (i >> 10) & 7;
        int gb   = (int)(i >> 13);
        int g = lane >> 2, tig = lane & 3;
        int m1 = gb * 128 + ws * 16 + g;
        int m2 = m1 + 8;
        int r1 = (m1 & 3) * Hh + (m1 >> 2);
        int r2 = (m2 & 3) * Hh + (m2 >> 2);
        int k0 = k8 * 8;
        float4 v;
        v.x = __uint_as_float(tf32r(Wx[(size_t)r1 * Dd + k0 + tig]));
        v.y = __uint_as_float(tf32r(Wx[(size_t)r2 * Dd + k0 + tig]));
        v.z = __uint_as_float(tf32r(Wx[(size_t)r1 * Dd + k0 + tig + 4]));
        v.w = __uint_as_float(tf32r(Wx[(size_t)r2 * Dd + k0 + tig + 4]));
        ((float4*)d_Axf)[i] = v;
    } else {
        size_t i = (size_t)(blk - 5120) * 256 + threadIdx.x;
        int lane = i & 31;
        int k8   = (i >> 5) & 127;
        int s    = (int)(i >> 12);
        int g = lane >> 2, tig = lane & 3;
        int d1 = s * 16 + g, d2 = d1 + 8;
        int k0 = k8 * 8;
        float4 v;
        v.x = __uint_as_float(tf32r(Wo[(size_t)d1 * Hh + k0 + tig]));
        v.y = __uint_as_float(tf32r(Wo[(size_t)d2 * Hh + k0 + tig]));
        v.z = __uint_as_float(tf32r(Wo[(size_t)d1 * Hh + k0 + tig + 4]));
        v.w = __uint_as_float(tf32r(Wo[(size_t)d2 * Hh + k0 + tig + 4]));
        ((float4*)d_Wof)[i] = v;
    }
}

// ---------------- GEMM 1 (tf32 mma): xg = inputs . Wx^T + bx + bh ---------------
// Grid (32, 4) x 256 thr.  CTA: 128 gate-cols x 64 batch, K=256, t = by + 4i.
// A-frags (gb slice, 128 KB) preloaded to dynamic smem; warp w owns n-group
// b in [w*8, w*8+8) and ALL 8 m-strips; B fragments via __ldg (L1, full sectors).
__global__ void __launch_bounds__(256) gemm_xg_mma(
    const float* __restrict__ inp, const float* __restrict__ bx,
    const float* __restrict__ bh)
{
    extern __shared__ __align__(16) float4 Axs[];   // [(k8*8+strip)*32 + lane]
    const int tid = threadIdx.x, w = tid >> 5, lane = tid & 31;
    const int g = lane >> 2, tig = lane & 3;
    const int gb = blockIdx.x;
    const int n0 = w * 8;

    for (int i = tid; i < 8192; i += 256) {
        int ln = i & 31, ws = (i >> 5) & 7, k8 = i >> 8;
        Axs[(k8 * 8 + ws) * 32 + ln] =
            ((const float4*)d_Axf)[(size_t)gb * 8192 + ws * 1024 + k8 * 32 + ln];
    }
    float bias1[8], bias2[8];
#pragma unroll
    for (int s = 0; s < 8; s++) {
        int m1 = gb * 128 + s * 16 + g, m2 = m1 + 8;
        int r1 = (m1 & 3) * Hh + (m1 >> 2), r2 = (m2 & 3) * Hh + (m2 >> 2);
        bias1[s] = bx[r1] + bh[r1];
        bias2[s] = bx[r2] + bh[r2];
    }
    __syncthreads();

    const float* brow = inp + ((size_t)(n0 + g) * Tt) * Dd + tig;

    for (int t = blockIdx.y; t < Tt; t += 4) {
        const float* bp = brow + (size_t)t * Dd;
        float acc[8][4];
#pragma unroll
        for (int s = 0; s < 8; s++)
#pragma unroll
            for (int q = 0; q < 4; q++) acc[s][q] = 0.f;

        unsigned Bf[2][16];
#pragma unroll
        for (int k8 = 0; k8 < 8; k8++) {
            Bf[0][k8 * 2]     = tf32r(__ldg(&bp[k8 * 8]));
            Bf[0][k8 * 2 + 1] = tf32r(__ldg(&bp[k8 * 8 + 4]));
        }
#pragma unroll
        for (int blk = 0; blk < 4; blk++) {
            const int cur = blk & 1;
            if (blk < 3) {
#pragma unroll
                for (int k8 = 0; k8 < 8; k8++) {
                    int kk = (blk + 1) * 8 + k8;
                    Bf[cur ^ 1][k8 * 2]     = tf32r(__ldg(&bp[kk * 8]));
                    Bf[cur ^ 1][k8 * 2 + 1] = tf32r(__ldg(&bp[kk * 8 + 4]));
                }
            }
#pragma unroll
            for (int k8 = 0; k8 < 8; k8++) {
                const int kg = blk * 8 + k8;
#pragma unroll
                for (int s = 0; s < 8; s++) {
                    float4 a4 = Axs[(kg * 8 + s) * 32 + lane];
                    MMA_TF32(acc[s], __float_as_uint(a4.x), __float_as_uint(a4.y),
                             __float_as_uint(a4.z), __float_as_uint(a4.w),
                             Bf[cur][k8 * 2], Bf[cur][k8 * 2 + 1]);
                }
            }
        }
#pragma unroll
        for (int s = 0; s < 8; s++) {
            int m1 = gb * 128 + s * 16 + g, m2 = m1 + 8;
            *(float2*)&d_xg[((size_t)t * Gg + m1) * 64 + n0 + tig * 2] =
                make_float2(acc[s][0] + bias1[s], acc[s][1] + bias1[s]);
            *(float2*)&d_xg[((size_t)t * Gg + m2) * 64 + n0 + tig * 2] =
                make_float2(acc[s][2] + bias2[s], acc[s][3] + bias2[s]);
        }
    }
}

// ---------------- software grid barrier ----------------------------------------
__device__ __forceinline__ void grid_sync()
{
    __syncthreads();
    if (threadIdx.x == 0) {
        __threadfence();
        volatile unsigned* vg = &d_bgen;
        unsigned g = *vg;
        unsigned prev = atomicAdd(&d_bcount, 1u);
        if (prev == NCTA - 1) {
            d_bcount = 0u;
            __threadfence();
            atomicAdd(&d_bgen, 1u);
        } else {
            while (*vg == g) { __nanosleep(64); }
        }
        __threadfence();
    }
    __syncthreads();
}

__device__ __forceinline__ float sigm(float x) { return 1.0f / (1.0f + expf(-x)); }

// ---------------- persistent LSTM recurrence (tf32 mma.sync, v2) ----------------
// 128 CTAs x 256 thr.  CTA owns 32 gate-cols; warp w owns n-group b in [w*8,+8),
// ALL 32 m (2 strips), full K=1024.  A-frags (step-invariant, 128 KB) preloaded
// into dynamic smem; B fragments streamed directly from h via __ldcg (100%
// sector use), software-pipelined.  No staging, no k-loop syncthreads.
#define DS_P 68
__global__ void __launch_bounds__(256, 1) lstm_mma()
{
    extern __shared__ __align__(16) float4 Afs[];    // [(k8*2+ms)*32 + lane]
    __shared__ __align__(16) float Ds[32 * DS_P];
    const int tid  = threadIdx.x;
    const int cta  = blockIdx.x;
    const int w    = tid >> 5, lane = tid & 31;
    const int g    = lane >> 2, tig = lane & 3;
    const int n0   = w * 8;
    const int nb   = n0 + g;
    const int pb   = tid & 63;
    const int jl0  = tid >> 6;
    float cs[2] = {0.f, 0.f};

    for (int i = tid; i < 8192; i += 256) {
        int ln = i & 31, ms = (i >> 5) & 1, k8 = i >> 6;
        Afs[(k8 * 2 + ms) * 32 + ln] =
            ((const float4*)d_Af)[(size_t)cta * 8192 + ms * 4096 + k8 * 32 + ln];
    }
    __syncthreads();

    for (int t = 0; t < Tt; t++) {
        const float* hcur = d_h2 + (size_t)(t & 1) * (Hh * Bb);
        float*       hnxt = d_h2 + (size_t)((t + 1) & 1) * (Hh * Bb);

        // prefetch xg for this thread's 2 (j, b) pairs (DRAM latency hidden)
        float xg0[4], xg1[4];
#pragma unroll
        for (int q = 0; q < 4; q++) {
            xg0[q] = d_xg[(((size_t)t * Hh + cta * 8 + jl0) * 4 + q) * Bb + pb];
            xg1[q] = d_xg[(((size_t)t * Hh + cta * 8 + jl0 + 4) * 4 + q) * Bb + pb];
        }

        float acc0[4] = {0.f, 0.f, 0.f, 0.f};
        float acc1[4] = {0.f, 0.f, 0.f, 0.f};

        unsigned Bf[2][16];
#pragma unroll
        for (int k8 = 0; k8 < 8; k8++) {
            Bf[0][k8 * 2]     = __float_as_uint(__ldcg(&hcur[(k8 * 8 + tig) * 64 + nb]));
            Bf[0][k8 * 2 + 1] = __float_as_uint(__ldcg(&hcur[(k8 * 8 + tig + 4) * 64 + nb]));
        }
#pragma unroll 1
        for (int blk = 0; blk < 16; blk++) {
            const int cur = blk & 1;
            if (blk < 15) {
#pragma unroll
                for (int k8 = 0; k8 < 8; k8++) {
                    int kk = (blk + 1) * 8 + k8;
                    Bf[cur ^ 1][k8 * 2] =
                        __float_as_uint(__ldcg(&hcur[(kk * 8 + tig) * 64 + nb]));
                    Bf[cur ^ 1][k8 * 2 + 1] =
                        __float_as_uint(__ldcg(&hcur[(kk * 8 + tig + 4) * 64 + nb]));
                }
            }
#pragma unroll
            for (int k8 = 0; k8 < 8; k8++) {
                const int kg = blk * 8 + k8;
                float4 aa = Afs[(kg * 2 + 0) * 32 + lane];
                float4 ab = Afs[(kg * 2 + 1) * 32 + lane];
                MMA_TF32(acc0, __float_as_uint(aa.x), __float_as_uint(aa.y),
                         __float_as_uint(aa.z), __float_as_uint(aa.w),
                         Bf[cur][k8 * 2], Bf[cur][k8 * 2 + 1]);
                MMA_TF32(acc1, __float_as_uint(ab.x), __float_as_uint(ab.y),
                         __float_as_uint(ab.z), __float_as_uint(ab.w),
                         Bf[cur][k8 * 2], Bf[cur][k8 * 2 + 1]);
            }
        }

        // D fragments -> smem (rows = local col m, cols = batch)
        *(float2*)&Ds[g * DS_P + n0 + tig * 2]        = make_float2(acc0[0], acc0[1]);
        *(float2*)&Ds[(g + 8) * DS_P + n0 + tig * 2]  = make_float2(acc0[2], acc0[3]);
        *(float2*)&Ds[(g + 16) * DS_P + n0 + tig * 2] = make_float2(acc1[0], acc1[1]);
        *(float2*)&Ds[(g + 24) * DS_P + n0 + tig * 2] = make_float2(acc1[2], acc1[3]);
        __syncthreads();

        // pointwise: 2 (j, b) pairs per thread; c in registers
#pragma unroll
        for (int pp = 0; pp < 2; pp++) {
            int jl = jl0 + pp * 4;
            const float* xf = pp ? xg1 : xg0;
            float gi = Ds[(jl * 4 + 0) * DS_P + pb] + xf[0];
            float gf = Ds[(jl * 4 + 1) * DS_P + pb] + xf[1];
            float gg = Ds[(jl * 4 + 2) * DS_P + pb] + xf[2];
            float go = Ds[(jl * 4 + 3) * DS_P + pb] + xf[3];
            float si = sigm(gi), sf = sigm(gf), sg = sigm(gg), so = sigm(go);
            float cn = cs[pp] * sf + si * sg;      // NOTE: sigmoid cell gate (per ref)
            cs[pp] = cn;
            float hn = so * tanhf(cn);
            int j = cta * 8 + jl;
            d_hsJ[((size_t)j * Tt + t) * 64 + pb] = hn;
            __stcg(&hnxt[j * 64 + pb], __uint_as_float(tf32r(hn)));
        }
        grid_sync();
    }
}

// ---------------- GEMM 3 (tf32 mma): outT[d][m'] = Wout . hs --------------------
#define HS_P 72
__global__ void __launch_bounds__(256) gemm_out_mma()
{
    __shared__ __align__(16) float hsm[2][64 * HS_P];
    const int tid = threadIdx.x, w = tid >> 5, lane = tid & 31;
    const int g = lane >> 2, tig = lane & 3;
    const int t = blockIdx.x;
    const int lk = tid >> 4, lf = tid & 15;
    const float4* Af1 = (const float4*)d_Wof + (size_t)w * 128 * 32 + lane;
    const float4* Af2 = (const float4*)d_Wof + (size_t)(w + 8) * 128 * 32 + lane;

    float acc[2][8][4];
#pragma unroll
    for (int sh = 0; sh < 2; sh++)
#pragma unroll
        for (int nbq = 0; nbq < 8; nbq++)
#pragma unroll
            for (int q = 0; q < 4; q++) acc[sh][nbq][q] = 0.f;

    float4 st[4];
#pragma unroll
    for (int p = 0; p < 4; p++) {
        int k = p * 16 + lk;
        st[p] = __ldcg((const float4*)&d_hsJ[((size_t)k * Tt + t) * 64 + lf * 4]);
    }

#pragma unroll 1
    for (int ch = 0; ch < 16; ch++) {
        const int buf = ch & 1;
#pragma unroll
        for (int p = 0; p < 4; p++)
            *(float4*)&hsm[buf][(p * 16 + lk) * HS_P + lf * 4] = st[p];
        __syncthreads();
        if (ch < 15) {
#pragma unroll
            for (int p = 0; p < 4; p++) {
                int k = (ch + 1) * 64 + p * 16 + lk;
                st[p] = __ldcg((const float4*)&d_hsJ[((size_t)k * Tt + t) * 64 + lf * 4]);
            }
        }
#pragma unroll
        for (int k8 = 0; k8 < 8; k8++) {
            const int kg = ch * 8 + k8;
            const int kl = k8 * 8;
            float4 af1 = __ldg(&Af1[kg * 32]);
            float4 af2 = __ldg(&Af2[kg * 32]);
#pragma unroll
            for (int nbq = 0; nbq < 8; nbq++) {
                unsigned b0 = tf32r(hsm[buf][(kl + tig) * HS_P + nbq * 8 + g]);
                unsigned b1 = tf32r(hsm[buf][(kl + tig + 4) * HS_P + nbq * 8 + g]);
                MMA_TF32(acc[0][nbq], __float_as_uint(af1.x), __float_as_uint(af1.y),
                         __float_as_uint(af1.z), __float_as_uint(af1.w), b0, b1);
                MMA_TF32(acc[1][nbq], __float_as_uint(af2.x), __float_as_uint(af2.y),
                         __float_as_uint(af2.z), __float_as_uint(af2.w), b0, b1);
            }
        }
        __syncthreads();
    }

#pragma unroll
    for (int sh = 0; sh < 2; sh++) {
        int dbase = (sh ? (w + 8) : w) * 16;
        int d1 = dbase + g, d2 = d1 + 8;
#pragma unroll
        for (int nbq = 0; nbq < 8; nbq++) {
            int bcol = nbq * 8 + tig * 2;
            *(float2*)&d_outT[(size_t)d1 * Mm + t * 64 + bcol] =
                make_float2(acc[sh][nbq][0], acc[sh][nbq][1]);
            *(float2*)&d_outT[(size_t)d2 * Mm + t * 64 + bcol] =
                make_float2(acc[sh][nbq][2], acc[sh][nbq][3]);
        }
    }
}

// ---------------- hidden = tanh(hs), [j][m'] -> [b][t][j] ----------------------
__global__ void tanhT_k(float* __restrict__ outH)
{
    __shared__ float tile[32][33];
    int m0 = blockIdx.x * 32;
    int j0 = blockIdx.y * 32;
    int tx = threadIdx.x, ty = threadIdx.y;
#pragma unroll
    for (int i = 0; i < 32; i += 8)
        tile[ty + i][tx] = d_hsJ[(size_t)(j0 + ty + i) * Mm + m0 + tx];
    __syncthreads();
    int t0 = m0 >> 6;
    int bbase = m0 & 63;
#pragma unroll
    for (int i = 0; i < 32; i += 8) {
        int mp = ty + i;
        int b = bbase + mp;
        outH[((size_t)b * Tt + t0) * Hh + j0 + tx] = tanhf(tile[tx][mp]);
    }
}

// ---------------- out = outT^T + bias: [d][m'] -> [b][t][d] ---------------------
__global__ void outT_k(const float* __restrict__ bo, float* __restrict__ outp)
{
    __shared__ float tile[32][33];
    int m0 = blockIdx.x * 32;
    int d0 = blockIdx.y * 32;
    int tx = threadIdx.x, ty = threadIdx.y;
#pragma unroll
    for (int i = 0; i < 32; i += 8)
        tile[ty + i][tx] = d_outT[(size_t)(d0 + ty + i) * Mm + m0 + tx];
    __syncthreads();
    int t0 = m0 >> 6;
    int bbase = m0 & 63;
    float bv = bo[d0 + tx];
#pragma unroll
    for (int i = 0; i < 32; i += 8) {
        int b = bbase + ty + i;
        outp[((size_t)b * Tt + t0) * Dd + d0 + tx] = tile[tx][ty + i] + bv;
    }
}

// ---------------- launch --------------------------------------------------------
extern "C" void kernel_launch(void* const* d_in, const int* in_sizes, int n_in,
                              void* d_out, int out_size)
{
    (void)in_sizes; (void)n_in; (void)out_size;
    const float* inp = (const float*)d_in[0];
    const float* Wx  = (const float*)d_in[1];
    const float* bx  = (const float*)d_in[2];
    const float* Wh  = (const float*)d_in[3];
    const float* bh  = (const float*)d_in[4];
    const float* Wo  = (const float*)d_in[5];
    const float* bo  = (const float*)d_in[6];
    float* out = (float*)d_out;
    float* outHidden = out + (size_t)Bb * Tt * Dd;

    const int frag_smem = 8192 * sizeof(float4);   // 131072 B
    cudaFuncSetAttribute(gemm_xg_mma,
                         cudaFuncAttributeMaxDynamicSharedMemorySize, frag_smem);
    cudaFuncSetAttribute(lstm_mma,
                         cudaFuncAttributeMaxDynamicSharedMemorySize, frag_smem);

    init_k<<<512, 256>>>();
    pack_all<<<5376, 256>>>(Wh, Wx, Wo);
    gemm_xg_mma<<<dim3(32, 4), 256, frag_smem>>>(inp, bx, bh);
    lstm_mma<<<NCTA, 256, frag_smem>>>();            // launch #4 -> gets profiled
    gemm_out_mma<<<Tt, 256>>>();
    tanhT_k<<<dim3(Mm / 32, Hh / 32), dim3(32, 8)>>>(outHidden);
    outT_k<<<dim3(Mm / 32, Dd / 32), dim3(32, 8)>>>(bo, out);
}

// round 8
// speedup vs baseline: 1.5238x; 1.5238x over previous
#include <cuda_runtime.h>
#include <math.h>

// Problem dims
#define Bb   64
#define Tt   512
#define Dd   256
#define Hh   1024
#define Gg   4096          // 4*H
#define Mm   32768         // B*T
#define NCTA 128

// ---------------- scratch (__device__ globals; no dynamic allocation) ----------
__device__ float d_xg[(size_t)Tt * Gg * Bb];      // [t][m=j*4+g][b]   512 MB
__device__ float d_Af[(size_t)Gg * Hh];           // Wh tf32 A-fragments, 16 MB
__device__ float d_Axf[(size_t)Gg * Dd];          // Wx tf32 A-fragments, 4 MB
__device__ float d_Wof[(size_t)Dd * Hh];          // Wout tf32 A-fragments, 1 MB
__device__ float d_hsJ[(size_t)Hh * Mm];          // [j][m'] , m'=t*64+b   128 MB
__device__ float d_outT[(size_t)Dd * Mm];         // out head, [d][m']     32 MB
__device__ float d_h2[2 * Hh * Bb];               // double-buffered h, [buf][k][b]
__device__ unsigned d_bcount;

__device__ __forceinline__ unsigned tf32r(float x)
{
    unsigned u;
    asm("cvt.rna.tf32.f32 %0, %1;" : "=r"(u) : "f"(x));
    return u;
}
__device__ __forceinline__ float tf32f(float x)
{
    return __uint_as_float(tf32r(x));
}
__device__ __forceinline__ float tanh_ap(float x)
{
    float y;
    asm("tanh.approx.f32 %0, %1;" : "=f"(y) : "f"(x));
    return y;
}

// tf32 mma: D(m16n8) += A(m16k8) * B(k8n8)
#define MMA_TF32(d, a0, a1, a2, a3, b0, b1)                                     \
    asm volatile("mma.sync.aligned.m16n8k8.row.col.f32.tf32.tf32.f32 "          \
                 "{%0,%1,%2,%3}, {%4,%5,%6,%7}, {%8,%9}, {%0,%1,%2,%3};"        \
                 : "+f"(d[0]), "+f"(d[1]), "+f"(d[2]), "+f"(d[3])               \
                 : "r"(a0), "r"(a1), "r"(a2), "r"(a3), "r"(b0), "r"(b1))

// ---------------- init: zero h state --------------------------------------------
__global__ void init_k()
{
    int i = blockIdx.x * blockDim.x + threadIdx.x;
    if (i < 2 * Hh * Bb) d_h2[i] = 0.0f;
}
__global__ void init_bar()
{
    if (threadIdx.x == 0) d_bcount = 0u;
}

// ---------------- combined weight-fragment packing ------------------------------
// blocks [0,4096): Wh frags   [4096,5120): Wx frags   [5120,5376): Wout frags
__global__ void pack_all(const float* __restrict__ Wh, const float* __restrict__ Wx,
                         const float* __restrict__ Wo)
{
    int blk = blockIdx.x;
    if (blk < 4096) {
        size_t i = (size_t)blk * 256 + threadIdx.x;
        int lane = i & 31;
        int kc   = (i >> 5) & 127;
        int ms   = (i >> 12) & 1;
        int cb   = (int)(i >> 13);
        int g = lane >> 2, tig = lane & 3;
        int m1 = ms * 16 + g, m2 = m1 + 8;
        int r1 = (m1 & 3) * Hh + cb * 8 + (m1 >> 2);
        int r2 = (m2 & 3) * Hh + cb * 8 + (m2 >> 2);
        int k0 = kc * 8;
        float4 v;
        v.x = __uint_as_float(tf32r(Wh[(size_t)r1 * Hh + k0 + tig]));
        v.y = __uint_as_float(tf32r(Wh[(size_t)r2 * Hh + k0 + tig]));
        v.z = __uint_as_float(tf32r(Wh[(size_t)r1 * Hh + k0 + tig + 4]));
        v.w = __uint_as_float(tf32r(Wh[(size_t)r2 * Hh + k0 + tig + 4]));
        ((float4*)d_Af)[i] = v;
    } else if (blk < 5120) {
        size_t i = (size_t)(blk - 4096) * 256 + threadIdx.x;
        int lane = i & 31;
        int k8   = (i >> 5) & 31;
        int ws   = (i >> 10) & 7;
        int gb   = (int)(i >> 13);
        int g = lane >> 2, tig = lane & 3;
        int m1 = gb * 128 + ws * 16 + g;
        int m2 = m1 + 8;
        int r1 = (m1 & 3) * Hh + (m1 >> 2);
        int r2 = (m2 & 3) * Hh + (m2 >> 2);
        int k0 = k8 * 8;
        float4 v;
        v.x = __uint_as_float(tf32r(Wx[(size_t)r1 * Dd + k0 + tig]));
        v.y = __uint_as_float(tf32r(Wx[(size_t)r2 * Dd + k0 + tig]));
        v.z = __uint_as_float(tf32r(Wx[(size_t)r1 * Dd + k0 + tig + 4]));
        v.w = __uint_as_float(tf32r(Wx[(size_t)r2 * Dd + k0 + tig + 4]));
        ((float4*)d_Axf)[i] = v;
    } else {
        size_t i = (size_t)(blk - 5120) * 256 + threadIdx.x;
        int lane = i & 31;
        int k8   = (i >> 5) & 127;
        int s    = (int)(i >> 12);
        int g = lane >> 2, tig = lane & 3;
        int d1 = s * 16 + g, d2 = d1 + 8;
        int k0 = k8 * 8;
        float4 v;
        v.x = __uint_as_float(tf32r(Wo[(size_t)d1 * Hh + k0 + tig]));
        v.y = __uint_as_float(tf32r(Wo[(size_t)d2 * Hh + k0 + tig]));
        v.z = __uint_as_float(tf32r(Wo[(size_t)d1 * Hh + k0 + tig + 4]));
        v.w = __uint_as_float(tf32r(Wo[(size_t)d2 * Hh + k0 + tig + 4]));
        ((float4*)d_Wof)[i] = v;
    }
}

// ---------------- GEMM 1 (tf32 mma): xg[t][m][b] = inputs . Wx^T + bx + bh ------
// Grid (32, 4) x 256 thr.  CTA: 128 gate-cols x 64 batch, K=256, TWO t per pass.
// Inputs staged [b][k] pitch 260 with cvt.rna (B-frag LDS conflict-free: 4g+tig).
#define XP 260
__global__ void __launch_bounds__(256) gemm_xg_mma(
    const float* __restrict__ inp, const float* __restrict__ bx,
    const float* __restrict__ bh)
{
    extern __shared__ float Bsm[];            // 2 * 64 * XP floats
    const int tid = threadIdx.x, w = tid >> 5, lane = tid & 31;
    const int g = lane >> 2, tig = lane & 3;
    const int gb = blockIdx.x;
    const int m1 = gb * 128 + w * 16 + g, m2 = m1 + 8;
    const int r1 = (m1 & 3) * Hh + (m1 >> 2), r2 = (m2 & 3) * Hh + (m2 >> 2);
    const float bias1 = bx[r1] + bh[r1];
    const float bias2 = bx[r2] + bh[r2];
    const float4* Af = (const float4*)d_Axf + (size_t)(gb * 8 + w) * 1024 + lane;
    const int brow = w * 8 + (lane >> 2);
    const int bq = lane & 3;

    for (int t0 = blockIdx.y * 2; t0 < Tt; t0 += 8) {
        // load two input t-slices -> smem [b][k], tf32-rounded
#pragma unroll
        for (int sl = 0; sl < 2; sl++) {
            const float4* src = (const float4*)(inp + ((size_t)brow * Tt + t0 + sl) * Dd);
            float* dst = Bsm + sl * 64 * XP + brow * XP;
#pragma unroll
            for (int i2 = 0; i2 < 16; i2++) {
                float4 v = __ldg(&src[i2 * 4 + bq]);
                v.x = tf32f(v.x); v.y = tf32f(v.y);
                v.z = tf32f(v.z); v.w = tf32f(v.w);
                *(float4*)&dst[(i2 * 4 + bq) * 4] = v;
            }
        }
        __syncthreads();

        float acc[2][8][4];
#pragma unroll
        for (int sl = 0; sl < 2; sl++)
#pragma unroll
            for (int nb = 0; nb < 8; nb++)
#pragma unroll
                for (int q = 0; q < 4; q++) acc[sl][nb][q] = 0.f;

#pragma unroll 4
        for (int k8 = 0; k8 < 32; k8++) {
            float4 a4 = __ldg(&Af[k8 * 32]);
            unsigned a0 = __float_as_uint(a4.x), a1 = __float_as_uint(a4.y);
            unsigned a2 = __float_as_uint(a4.z), a3 = __float_as_uint(a4.w);
            const int kl = k8 * 8;
#pragma unroll
            for (int nb = 0; nb < 8; nb++) {
#pragma unroll
                for (int sl = 0; sl < 2; sl++) {
                    const float* bp = Bsm + sl * 64 * XP + (nb * 8 + g) * XP + kl + tig;
                    unsigned b0 = __float_as_uint(bp[0]);
                    unsigned b1 = __float_as_uint(bp[4]);
                    MMA_TF32(acc[sl][nb], a0, a1, a2, a3, b0, b1);
                }
            }
        }
#pragma unroll
        for (int sl = 0; sl < 2; sl++) {
            int t = t0 + sl;
#pragma unroll
            for (int nb = 0; nb < 8; nb++) {
                *(float2*)&d_xg[((size_t)t * Gg + m1) * 64 + nb * 8 + tig * 2] =
                    make_float2(acc[sl][nb][0] + bias1, acc[sl][nb][1] + bias1);
                *(float2*)&d_xg[((size_t)t * Gg + m2) * 64 + nb * 8 + tig * 2] =
                    make_float2(acc[sl][nb][2] + bias2, acc[sl][nb][3] + bias2);
            }
        }
        __syncthreads();
    }
}

// ---------------- software grid barrier (monotonic counter, acq/rel) ------------
__device__ __forceinline__ void grid_sync(unsigned target)
{
    __syncthreads();
    if (threadIdx.x == 0) {
        asm volatile("red.release.gpu.global.add.u32 [%0], 1;"
                     :: "l"(&d_bcount) : "memory");
        unsigned c;
        do {
            asm volatile("ld.acquire.gpu.global.u32 %0, [%1];"
                         : "=r"(c) : "l"(&d_bcount) : "memory");
        } while (c < target);
    }
    __syncthreads();
}

__device__ __forceinline__ float sigm(float x) { return 1.0f / (1.0f + expf(-x)); }

// ---------------- persistent LSTM recurrence (tf32 mma.sync, R6 structure) ------
// 128 CTAs x 256 thr (8 warps).  CTA owns 32 gate-cols, N=64, K=1024.
// Warp w: m-strip (w&1)*16, n-strip (w>>1)*16.  h staged via smem in 16
// double-buffered k=64 chunks; A-frags via __ldg (L1-resident); D -> smem ->
// register pointwise; c in registers; ONE grid barrier per step.
#define HS_P 72
#define DS_P 68
__global__ void __launch_bounds__(256, 1) lstm_mma()
{
    __shared__ __align__(16) float hs[2][64 * HS_P];
    __shared__ __align__(16) float Ds[32 * DS_P];
    const int tid  = threadIdx.x;
    const int cta  = blockIdx.x;
    const int w    = tid >> 5, lane = tid & 31;
    const int g    = lane >> 2, tig = lane & 3;
    const int ms   = w & 1;
    const int n0   = (w >> 1) * 16;
    const int pb   = tid & 63;
    const int jl0  = tid >> 6;
    const float4* Af = (const float4*)d_Af + ((size_t)cta * 2 + ms) * 4096 + lane;
    float cs[2] = {0.f, 0.f};

    for (int t = 0; t < Tt; t++) {
        const float* hcur = d_h2 + (size_t)(t & 1) * (Hh * Bb);
        float*       hnxt = d_h2 + (size_t)((t + 1) & 1) * (Hh * Bb);

        // prefetch xg for this thread's 2 (j, b) pairs (DRAM latency hidden)
        float xg0[4], xg1[4];
#pragma unroll
        for (int q = 0; q < 4; q++) {
            xg0[q] = d_xg[(((size_t)t * Hh + cta * 8 + jl0) * 4 + q) * Bb + pb];
            xg1[q] = d_xg[(((size_t)t * Hh + cta * 8 + jl0 + 4) * 4 + q) * Bb + pb];
        }

        float acc0[4] = {0.f, 0.f, 0.f, 0.f};
        float acc1[4] = {0.f, 0.f, 0.f, 0.f};

        float4 st[4];
#pragma unroll
        for (int p = 0; p < 4; p++)
            st[p] = __ldcg((const float4*)hcur + p * 256 + tid);

#pragma unroll 1
        for (int ch = 0; ch < 16; ch++) {
            const int buf = ch & 1;
#pragma unroll
            for (int p = 0; p < 4; p++) {
                int idx = p * 256 + tid;
                *(float4*)&hs[buf][(idx >> 4) * HS_P + (idx & 15) * 4] = st[p];
            }
            __syncthreads();
            if (ch < 15) {
#pragma unroll
                for (int p = 0; p < 4; p++)
                    st[p] = __ldcg((const float4*)(hcur + (ch + 1) * 64 * 64) + p * 256 + tid);
            }
#pragma unroll
            for (int k8 = 0; k8 < 8; k8++) {
                float4 a4 = __ldg(&Af[(ch * 8 + k8) * 32]);
                unsigned a0 = __float_as_uint(a4.x), a1 = __float_as_uint(a4.y);
                unsigned a2 = __float_as_uint(a4.z), a3 = __float_as_uint(a4.w);
                const int kl = k8 * 8;
                unsigned b0 = __float_as_uint(hs[buf][(kl + tig) * HS_P + n0 + g]);
                unsigned b1 = __float_as_uint(hs[buf][(kl + tig + 4) * HS_P + n0 + g]);
                unsigned b2 = __float_as_uint(hs[buf][(kl + tig) * HS_P + n0 + 8 + g]);
                unsigned b3 = __float_as_uint(hs[buf][(kl + tig + 4) * HS_P + n0 + 8 + g]);
                MMA_TF32(acc0, a0, a1, a2, a3, b0, b1);
                MMA_TF32(acc1, a0, a1, a2, a3, b2, b3);
            }
        }

        // D fragments -> smem (rows = local col m, cols = batch)
        {
            int r1 = ms * 16 + g, r2 = r1 + 8;
            *(float2*)&Ds[r1 * DS_P + n0 + tig * 2]     = make_float2(acc0[0], acc0[1]);
            *(float2*)&Ds[r2 * DS_P + n0 + tig * 2]     = make_float2(acc0[2], acc0[3]);
            *(float2*)&Ds[r1 * DS_P + n0 + 8 + tig * 2] = make_float2(acc1[0], acc1[1]);
            *(float2*)&Ds[r2 * DS_P + n0 + 8 + tig * 2] = make_float2(acc1[2], acc1[3]);
        }
        __syncthreads();

        // pointwise: 2 (j, b) pairs per thread; c in registers
#pragma unroll
        for (int pp = 0; pp < 2; pp++) {
            int jl = jl0 + pp * 4;
            const float* xf = pp ? xg1 : xg0;
            float gi = Ds[(jl * 4 + 0) * DS_P + pb] + xf[0];
            float gf = Ds[(jl * 4 + 1) * DS_P + pb] + xf[1];
            float gg = Ds[(jl * 4 + 2) * DS_P + pb] + xf[2];
            float go = Ds[(jl * 4 + 3) * DS_P + pb] + xf[3];
            float si = sigm(gi), sf = sigm(gf), sg = sigm(gg), so = sigm(go);
            float cn = cs[pp] * sf + si * sg;      // NOTE: sigmoid cell gate (per ref)
            cs[pp] = cn;
            float hn = so * tanhf(cn);
            int j = cta * 8 + jl;
            d_hsJ[((size_t)j * Tt + t) * 64 + pb] = hn;
            __stcg(&hnxt[j * 64 + pb], __uint_as_float(tf32r(hn)));
        }
        grid_sync((unsigned)NCTA * (t + 1));
    }
}

// ---------------- GEMM 3 (tf32 mma): outT[d][m'] = Wout . hs --------------------
__global__ void __launch_bounds__(256) gemm_out_mma()
{
    __shared__ __align__(16) float hsm[2][64 * HS_P];
    const int tid = threadIdx.x, w = tid >> 5, lane = tid & 31;
    const int g = lane >> 2, tig = lane & 3;
    const int t = blockIdx.x;
    const int lk = tid >> 4, lf = tid & 15;
    const float4* Af1 = (const float4*)d_Wof + (size_t)w * 128 * 32 + lane;
    const float4* Af2 = (const float4*)d_Wof + (size_t)(w + 8) * 128 * 32 + lane;

    float acc[2][8][4];
#pragma unroll
    for (int sh = 0; sh < 2; sh++)
#pragma unroll
        for (int nbq = 0; nbq < 8; nbq++)
#pragma unroll
            for (int q = 0; q < 4; q++) acc[sh][nbq][q] = 0.f;

    float4 st[4];
#pragma unroll
    for (int p = 0; p < 4; p++) {
        int k = p * 16 + lk;
        st[p] = __ldcg((const float4*)&d_hsJ[((size_t)k * Tt + t) * 64 + lf * 4]);
    }

#pragma unroll 1
    for (int ch = 0; ch < 16; ch++) {
        const int buf = ch & 1;
#pragma unroll
        for (int p = 0; p < 4; p++)
            *(float4*)&hsm[buf][(p * 16 + lk) * HS_P + lf * 4] = st[p];
        __syncthreads();
        if (ch < 15) {
#pragma unroll
            for (int p = 0; p < 4; p++) {
                int k = (ch + 1) * 64 + p * 16 + lk;
                st[p] = __ldcg((const float4*)&d_hsJ[((size_t)k * Tt + t) * 64 + lf * 4]);
            }
        }
#pragma unroll
        for (int k8 = 0; k8 < 8; k8++) {
            const int kg = ch * 8 + k8;
            const int kl = k8 * 8;
            float4 af1 = __ldg(&Af1[kg * 32]);
            float4 af2 = __ldg(&Af2[kg * 32]);
#pragma unroll
            for (int nbq = 0; nbq < 8; nbq++) {
                unsigned b0 = tf32r(hsm[buf][(kl + tig) * HS_P + nbq * 8 + g]);
                unsigned b1 = tf32r(hsm[buf][(kl + tig + 4) * HS_P + nbq * 8 + g]);
                MMA_TF32(acc[0][nbq], __float_as_uint(af1.x), __float_as_uint(af1.y),
                         __float_as_uint(af1.z), __float_as_uint(af1.w), b0, b1);
                MMA_TF32(acc[1][nbq], __float_as_uint(af2.x), __float_as_uint(af2.y),
                         __float_as_uint(af2.z), __float_as_uint(af2.w), b0, b1);
            }
        }
        __syncthreads();
    }

#pragma unroll
    for (int sh = 0; sh < 2; sh++) {
        int dbase = (sh ? (w + 8) : w) * 16;
        int d1 = dbase + g, d2 = d1 + 8;
#pragma unroll
        for (int nbq = 0; nbq < 8; nbq++) {
            int bcol = nbq * 8 + tig * 2;
            *(float2*)&d_outT[(size_t)d1 * Mm + t * 64 + bcol] =
                make_float2(acc[sh][nbq][0], acc[sh][nbq][1]);
            *(float2*)&d_outT[(size_t)d2 * Mm + t * 64 + bcol] =
                make_float2(acc[sh][nbq][2], acc[sh][nbq][3]);
        }
    }
}

// ---------------- hidden = tanh(hs), [j][m'] -> [b][t][j] ----------------------
__global__ void tanhT_k(float* __restrict__ outH)
{
    __shared__ float tile[32][33];
    int m0 = blockIdx.x * 32;
    int j0 = blockIdx.y * 32;
    int tx = threadIdx.x, ty = threadIdx.y;
#pragma unroll
    for (int i = 0; i < 32; i += 8)
        tile[ty + i][tx] = d_hsJ[(size_t)(j0 + ty + i) * Mm + m0 + tx];
    __syncthreads();
    int t0 = m0 >> 6;
    int bbase = m0 & 63;
#pragma unroll
    for (int i = 0; i < 32; i += 8) {
        int mp = ty + i;
        int b = bbase + mp;
        outH[((size_t)b * Tt + t0) * Hh + j0 + tx] = tanh_ap(tile[tx][mp]);
    }
}

// ---------------- out = outT^T + bias: [d][m'] -> [b][t][d] ---------------------
__global__ void outT_k(const float* __restrict__ bo, float* __restrict__ outp)
{
    __shared__ float tile[32][33];
    int m0 = blockIdx.x * 32;
    int d0 = blockIdx.y * 32;
    int tx = threadIdx.x, ty = threadIdx.y;
#pragma unroll
    for (int i = 0; i < 32; i += 8)
        tile[ty + i][tx] = d_outT[(size_t)(d0 + ty + i) * Mm + m0 + tx];
    __syncthreads();
    int t0 = m0 >> 6;
    int bbase = m0 & 63;
    float bv = bo[d0 + tx];
#pragma unroll
    for (int i = 0; i < 32; i += 8) {
        int b = bbase + ty + i;
        outp[((size_t)b * Tt + t0) * Dd + d0 + tx] = tile[tx][ty + i] + bv;
    }
}

// ---------------- launch --------------------------------------------------------
extern "C" void kernel_launch(void* const* d_in, const int* in_sizes, int n_in,
                              void* d_out, int out_size)
{
    (void)in_sizes; (void)n_in; (void)out_size;
    const float* inp = (const float*)d_in[0];
    const float* Wx  = (const float*)d_in[1];
    const float* bx  = (const float*)d_in[2];
    const float* Wh  = (const float*)d_in[3];
    const float* bh  = (const float*)d_in[4];
    const float* Wo  = (const float*)d_in[5];
    const float* bo  = (const float*)d_in[6];
    float* out = (float*)d_out;
    float* outHidden = out + (size_t)Bb * Tt * Dd;

    const int xg_smem = 2 * 64 * XP * sizeof(float);   // 133,120 B
    cudaFuncSetAttribute(gemm_xg_mma,
                         cudaFuncAttributeMaxDynamicSharedMemorySize, xg_smem);

    init_k<<<512, 256>>>();                                // #1
    pack_all<<<5376, 256>>>(Wh, Wx, Wo);                   // #2
    init_bar<<<1, 32>>>();                                 // #3
    gemm_xg_mma<<<dim3(32, 4), 256, xg_smem>>>(inp, bx, bh);  // #4 -> profiled
    lstm_mma<<<NCTA, 256>>>();                             // #5
    gemm_out_mma<<<Tt, 256>>>();                           // #6
    tanhT_k<<<dim3(Mm / 32, Hh / 32), dim3(32, 8)>>>(outHidden);
    outT_k<<<dim3(Mm / 32, Dd / 32), dim3(32, 8)>>>(bo, out);
}

// round 10
// speedup vs baseline: 2.0012x; 1.3133x over previous
#include <cuda_runtime.h>
#include <cuda_fp16.h>
#include <math.h>

// Problem dims
#define Bb   64
#define Tt   512
#define Dd   256
#define Hh   1024
#define Gg   4096          // 4*H
#define Mm   32768         // B*T
#define NCTA 128

// ---------------- scratch (__device__ globals; no dynamic allocation) ----------
__device__ float d_xg[(size_t)Tt * Gg * Bb];      // [t][m=j*4+g][b]   512 MB
__device__ uint4 d_Afh[(size_t)NCTA * 2 * 64 * 32]; // Wh fp16 A-frags, 8 MB
__device__ float d_Axf[(size_t)Gg * Dd];          // Wx tf32 A-fragments, 4 MB
__device__ float d_Wof[(size_t)Dd * Hh];          // Wout tf32 A-fragments, 1 MB
__device__ float d_hsJ[(size_t)Hh * Mm];          // [j][m'] , m'=t*64+b   128 MB
__device__ float d_outT[(size_t)Dd * Mm];         // out head, [d][m']     32 MB
__device__ unsigned d_h2h[2 * 512 * Bb];          // double-buffered h, half2 [buf][k/2][b]
__device__ unsigned d_bcount;

__device__ __forceinline__ unsigned tf32r(float x)
{
    unsigned u;
    asm("cvt.rna.tf32.f32 %0, %1;" : "=r"(u) : "f"(x));
    return u;
}
__device__ __forceinline__ float tf32f(float x) { return __uint_as_float(tf32r(x)); }
__device__ __forceinline__ float tanh_ap(float x)
{
    float y;
    asm("tanh.approx.f32 %0, %1;" : "=f"(y) : "f"(x));
    return y;
}
__device__ __forceinline__ unsigned pkh2(float lo, float hi)
{
    __half2 h = __floats2half2_rn(lo, hi);
    return *(unsigned*)&h;
}

// tf32 mma: D(m16n8) += A(m16k8) * B(k8n8)
#define MMA_TF32(d, a0, a1, a2, a3, b0, b1)                                     \
    asm volatile("mma.sync.aligned.m16n8k8.row.col.f32.tf32.tf32.f32 "          \
                 "{%0,%1,%2,%3}, {%4,%5,%6,%7}, {%8,%9}, {%0,%1,%2,%3};"        \
                 : "+f"(d[0]), "+f"(d[1]), "+f"(d[2]), "+f"(d[3])               \
                 : "r"(a0), "r"(a1), "r"(a2), "r"(a3), "r"(b0), "r"(b1))

// fp16 mma: D(m16n8) += A(m16k16) * B(k16n8), fp32 accum
#define MMA_F16(d, a0, a1, a2, a3, b0, b1)                                      \
    asm volatile("mma.sync.aligned.m16n8k16.row.col.f32.f16.f16.f32 "           \
                 "{%0,%1,%2,%3}, {%4,%5,%6,%7}, {%8,%9}, {%0,%1,%2,%3};"        \
                 : "+f"(d[0]), "+f"(d[1]), "+f"(d[2]), "+f"(d[3])               \
                 : "r"(a0), "r"(a1), "r"(a2), "r"(a3), "r"(b0), "r"(b1))

// ---------------- init: zero h state, reset barrier -----------------------------
__global__ void init_k()
{
    int i = blockIdx.x * blockDim.x + threadIdx.x;
    if (i < 2 * 512 * Bb) d_h2h[i] = 0u;
    if (i == 0) d_bcount = 0u;
}

// ---------------- combined weight-fragment packing ------------------------------
// blocks [0,2048): Wh fp16   [2048,3072): Wx tf32   [3072,3328): Wout tf32
__global__ void pack_all(const float* __restrict__ Wh, const float* __restrict__ Wx,
                         const float* __restrict__ Wo)
{
    int blk = blockIdx.x;
    if (blk < 2048) {
        // fp16 A frag (m16n8k16): uint4 i = ((cb*2+ms)*64 + k16)*32 + lane
        size_t i = (size_t)blk * 256 + threadIdx.x;   // 524,288 total
        int lane = i & 31;
        int k16  = (i >> 5) & 63;
        int ms   = (i >> 11) & 1;
        int cb   = (int)(i >> 12);
        int g = lane >> 2, tig = lane & 3;
        int m1 = ms * 16 + g, m2 = m1 + 8;
        int r1 = (m1 & 3) * Hh + cb * 8 + (m1 >> 2);
        int r2 = (m2 & 3) * Hh + cb * 8 + (m2 >> 2);
        int k0 = k16 * 16 + tig * 2;
        uint4 v;
        v.x = pkh2(Wh[(size_t)r1 * Hh + k0],     Wh[(size_t)r1 * Hh + k0 + 1]);
        v.y = pkh2(Wh[(size_t)r2 * Hh + k0],     Wh[(size_t)r2 * Hh + k0 + 1]);
        v.z = pkh2(Wh[(size_t)r1 * Hh + k0 + 8], Wh[(size_t)r1 * Hh + k0 + 9]);
        v.w = pkh2(Wh[(size_t)r2 * Hh + k0 + 8], Wh[(size_t)r2 * Hh + k0 + 9]);
        d_Afh[i] = v;
    } else if (blk < 3072) {
        size_t i = (size_t)(blk - 2048) * 256 + threadIdx.x;
        int lane = i & 31;
        int k8   = (i >> 5) & 31;
        int ws   = (i >> 10) & 7;
        int gb   = (int)(i >> 13);
        int g = lane >> 2, tig = lane & 3;
        int m1 = gb * 128 + ws * 16 + g;
        int m2 = m1 + 8;
        int r1 = (m1 & 3) * Hh + (m1 >> 2);
        int r2 = (m2 & 3) * Hh + (m2 >> 2);
        int k0 = k8 * 8;
        float4 v;
        v.x = __uint_as_float(tf32r(Wx[(size_t)r1 * Dd + k0 + tig]));
        v.y = __uint_as_float(tf32r(Wx[(size_t)r2 * Dd + k0 + tig]));
        v.z = __uint_as_float(tf32r(Wx[(size_t)r1 * Dd + k0 + tig + 4]));
        v.w = __uint_as_float(tf32r(Wx[(size_t)r2 * Dd + k0 + tig + 4]));
        ((float4*)d_Axf)[i] = v;
    } else {
        size_t i = (size_t)(blk - 3072) * 256 + threadIdx.x;
        int lane = i & 31;
        int k8   = (i >> 5) & 127;
        int s    = (int)(i >> 12);
        int g = lane >> 2, tig = lane & 3;
        int d1 = s * 16 + g, d2 = d1 + 8;
        int k0 = k8 * 8;
        float4 v;
        v.x = __uint_as_float(tf32r(Wo[(size_t)d1 * Hh + k0 + tig]));
        v.y = __uint_as_float(tf32r(Wo[(size_t)d2 * Hh + k0 + tig]));
        v.z = __uint_as_float(tf32r(Wo[(size_t)d1 * Hh + k0 + tig + 4]));
        v.w = __uint_as_float(tf32r(Wo[(size_t)d2 * Hh + k0 + tig + 4]));
        ((float4*)d_Wof)[i] = v;
    }
}

// ---------------- GEMM 1 (tf32 mma): xg[t][m][b] = inputs . Wx^T + bx + bh ------
#define XP 260
__global__ void __launch_bounds__(256) gemm_xg_mma(
    const float* __restrict__ inp, const float* __restrict__ bx,
    const float* __restrict__ bh)
{
    extern __shared__ float Bsm[];            // 2 * 64 * XP floats
    const int tid = threadIdx.x, w = tid >> 5, lane = tid & 31;
    const int g = lane >> 2, tig = lane & 3;
    const int gb = blockIdx.x;
    const int m1 = gb * 128 + w * 16 + g, m2 = m1 + 8;
    const int r1 = (m1 & 3) * Hh + (m1 >> 2), r2 = (m2 & 3) * Hh + (m2 >> 2);
    const float bias1 = bx[r1] + bh[r1];
    const float bias2 = bx[r2] + bh[r2];
    const float4* Af = (const float4*)d_Axf + (size_t)(gb * 8 + w) * 1024 + lane;
    const int brow = w * 8 + (lane >> 2);
    const int bq = lane & 3;

    for (int t0 = blockIdx.y * 2; t0 < Tt; t0 += 8) {
#pragma unroll
        for (int sl = 0; sl < 2; sl++) {
            const float4* src = (const float4*)(inp + ((size_t)brow * Tt + t0 + sl) * Dd);
            float* dst = Bsm + sl * 64 * XP + brow * XP;
#pragma unroll
            for (int i2 = 0; i2 < 16; i2++) {
                float4 v = __ldg(&src[i2 * 4 + bq]);
                v.x = tf32f(v.x); v.y = tf32f(v.y);
                v.z = tf32f(v.z); v.w = tf32f(v.w);
                *(float4*)&dst[(i2 * 4 + bq) * 4] = v;
            }
        }
        __syncthreads();

        float acc[2][8][4];
#pragma unroll
        for (int sl = 0; sl < 2; sl++)
#pragma unroll
            for (int nb = 0; nb < 8; nb++)
#pragma unroll
                for (int q = 0; q < 4; q++) acc[sl][nb][q] = 0.f;

#pragma unroll 4
        for (int k8 = 0; k8 < 32; k8++) {
            float4 a4 = __ldg(&Af[k8 * 32]);
            unsigned a0 = __float_as_uint(a4.x), a1 = __float_as_uint(a4.y);
            unsigned a2 = __float_as_uint(a4.z), a3 = __float_as_uint(a4.w);
            const int kl = k8 * 8;
#pragma unroll
            for (int nb = 0; nb < 8; nb++) {
#pragma unroll
                for (int sl = 0; sl < 2; sl++) {
                    const float* bp = Bsm + sl * 64 * XP + (nb * 8 + g) * XP + kl + tig;
                    unsigned b0 = __float_as_uint(bp[0]);
                    unsigned b1 = __float_as_uint(bp[4]);
                    MMA_TF32(acc[sl][nb], a0, a1, a2, a3, b0, b1);
                }
            }
        }
#pragma unroll
        for (int sl = 0; sl < 2; sl++) {
            int t = t0 + sl;
#pragma unroll
            for (int nb = 0; nb < 8; nb++) {
                *(float2*)&d_xg[((size_t)t * Gg + m1) * 64 + nb * 8 + tig * 2] =
                    make_float2(acc[sl][nb][0] + bias1, acc[sl][nb][1] + bias1);
                *(float2*)&d_xg[((size_t)t * Gg + m2) * 64 + nb * 8 + tig * 2] =
                    make_float2(acc[sl][nb][2] + bias2, acc[sl][nb][3] + bias2);
            }
        }
        __syncthreads();
    }
}

// ---------------- software grid barrier (monotonic counter, acq/rel) ------------
__device__ __forceinline__ void grid_sync(unsigned target)
{
    __syncthreads();
    if (threadIdx.x == 0) {
        asm volatile("red.release.gpu.global.add.u32 [%0], 1;"
                     :: "l"(&d_bcount) : "memory");
        unsigned c;
        do {
            asm volatile("ld.acquire.gpu.global.u32 %0, [%1];"
                         : "=r"(c) : "l"(&d_bcount) : "memory");
        } while (c < target);
    }
    __syncthreads();
}

__device__ __forceinline__ float sigm(float x) { return 1.0f / (1.0f + expf(-x)); }

// ---------------- persistent LSTM recurrence (fp16 m16n8k16 mma) ----------------
// 128 CTAs x 256 thr (8 warps).  CTA owns 32 gate-cols, N=64, K=1024.
// Warp w: m-strip (w&1)*16, n-strip (w>>1)*16.  h as half2 [k/2][b]; staged in
// 16 double-buffered k=64 chunks (32 half2-rows x 64 words, pitch 72 ->
// B-frag banks 8*tig+g, conflict-free).  A-frags fp16 via __ldg; D -> smem ->
// register pointwise; c in registers; ONE grid barrier per step.
#define HP2 72
#define DS_P 68
__global__ void __launch_bounds__(256, 1) lstm_mma()
{
    __shared__ __align__(16) unsigned hs2[2][32 * HP2];   // half2 words
    __shared__ __align__(16) float Ds[32 * DS_P];
    const int tid  = threadIdx.x;
    const int cta  = blockIdx.x;
    const int w    = tid >> 5, lane = tid & 31;
    const int g    = lane >> 2, tig = lane & 3;
    const int ms   = w & 1;
    const int n0   = (w >> 1) * 16;
    const int pb   = tid & 63;           // pointwise batch
    const int jl0  = tid >> 6;           // pointwise j-pair (2*jl0, 2*jl0+1)
    const uint4* Af = d_Afh + ((size_t)cta * 2 + ms) * 64 * 32 + lane;
    float cs[2] = {0.f, 0.f};

    for (int t = 0; t < Tt; t++) {
        const unsigned* hcur = d_h2h + (size_t)(t & 1) * (512 * Bb);
        unsigned*       hnxt = d_h2h + (size_t)((t + 1) & 1) * (512 * Bb);

        // prefetch xg for this thread's 2 (j, b) pairs (DRAM latency hidden)
        float xg0[4], xg1[4];
#pragma unroll
        for (int q = 0; q < 4; q++) {
            xg0[q] = d_xg[(((size_t)t * Hh + cta * 8 + 2 * jl0) * 4 + q) * Bb + pb];
            xg1[q] = d_xg[(((size_t)t * Hh + cta * 8 + 2 * jl0 + 1) * 4 + q) * Bb + pb];
        }

        float acc0[4] = {0.f, 0.f, 0.f, 0.f};
        float acc1[4] = {0.f, 0.f, 0.f, 0.f};

        // preload chunk 0: 32 half2-rows x 64 b = 2048 words = 512 uint4
        uint4 st[2];
#pragma unroll
        for (int p = 0; p < 2; p++)
            st[p] = __ldcg((const uint4*)hcur + p * 256 + tid);

#pragma unroll 1
        for (int ch = 0; ch < 16; ch++) {
            const int buf = ch & 1;
#pragma unroll
            for (int p = 0; p < 2; p++) {
                int idx = p * 256 + tid;                 // uint4 index in chunk
                *(uint4*)&hs2[buf][(idx >> 4) * HP2 + (idx & 15) * 4] = st[p];
            }
            __syncthreads();
            if (ch < 15) {
#pragma unroll
                for (int p = 0; p < 2; p++)
                    st[p] = __ldcg((const uint4*)hcur + (ch + 1) * 512 + p * 256 + tid);
            }
            // 4 k16 iterations per chunk
#pragma unroll
            for (int k16 = 0; k16 < 4; k16++) {
                uint4 a4 = __ldg(&Af[(ch * 4 + k16) * 32]);
                const int kb = k16 * 8;
                unsigned b0 = hs2[buf][(kb + tig) * HP2 + n0 + g];
                unsigned b1 = hs2[buf][(kb + tig + 4) * HP2 + n0 + g];
                unsigned b2 = hs2[buf][(kb + tig) * HP2 + n0 + 8 + g];
                unsigned b3 = hs2[buf][(kb + tig + 4) * HP2 + n0 + 8 + g];
                MMA_F16(acc0, a4.x, a4.y, a4.z, a4.w, b0, b1);
                MMA_F16(acc1, a4.x, a4.y, a4.z, a4.w, b2, b3);
            }
        }

        // D fragments -> smem (rows = local col m, cols = batch)
        {
            int r1 = ms * 16 + g, r2 = r1 + 8;
            *(float2*)&Ds[r1 * DS_P + n0 + tig * 2]     = make_float2(acc0[0], acc0[1]);
            *(float2*)&Ds[r2 * DS_P + n0 + tig * 2]     = make_float2(acc0[2], acc0[3]);
            *(float2*)&Ds[r1 * DS_P + n0 + 8 + tig * 2] = make_float2(acc1[0], acc1[1]);
            *(float2*)&Ds[r2 * DS_P + n0 + 8 + tig * 2] = make_float2(acc1[2], acc1[3]);
        }
        __syncthreads();

        // pointwise: adjacent j-pair per thread; c in registers
        float hn[2];
#pragma unroll
        for (int pp = 0; pp < 2; pp++) {
            int jl = 2 * jl0 + pp;
            const float* xf = pp ? xg1 : xg0;
            float gi = Ds[(jl * 4 + 0) * DS_P + pb] + xf[0];
            float gf = Ds[(jl * 4 + 1) * DS_P + pb] + xf[1];
            float gg = Ds[(jl * 4 + 2) * DS_P + pb] + xf[2];
            float go = Ds[(jl * 4 + 3) * DS_P + pb] + xf[3];
            float si = sigm(gi), sf = sigm(gf), sg = sigm(gg), so = sigm(go);
            float cn = cs[pp] * sf + si * sg;      // NOTE: sigmoid cell gate (per ref)
            cs[pp] = cn;
            hn[pp] = so * tanhf(cn);
            int j = cta * 8 + jl;
            d_hsJ[((size_t)j * Tt + t) * 64 + pb] = hn[pp];
        }
        __stcg(&hnxt[(cta * 4 + jl0) * 64 + pb], pkh2(hn[0], hn[1]));
        grid_sync((unsigned)NCTA * (t + 1));
    }
}

// ---------------- GEMM 3 (tf32 mma): outT[d][m'] = Wout . hs --------------------
#define HS_P 72
__global__ void __launch_bounds__(256) gemm_out_mma()
{
    __shared__ __align__(16) float hsm[2][64 * HS_P];
    const int tid = threadIdx.x, w = tid >> 5, lane = tid & 31;
    const int g = lane >> 2, tig = lane & 3;
    const int t = blockIdx.x;
    const int lk = tid >> 4, lf = tid & 15;
    const float4* Af1 = (const float4*)d_Wof + (size_t)w * 128 * 32 + lane;
    const float4* Af2 = (const float4*)d_Wof + (size_t)(w + 8) * 128 * 32 + lane;

    float acc[2][8][4];
#pragma unroll
    for (int sh = 0; sh < 2; sh++)
#pragma unroll
        for (int nbq = 0; nbq < 8; nbq++)
#pragma unroll
            for (int q = 0; q < 4; q++) acc[sh][nbq][q] = 0.f;

    float4 st[4];
#pragma unroll
    for (int p = 0; p < 4; p++) {
        int k = p * 16 + lk;
        st[p] = __ldcg((const float4*)&d_hsJ[((size_t)k * Tt + t) * 64 + lf * 4]);
    }

#pragma unroll 1
    for (int ch = 0; ch < 16; ch++) {
        const int buf = ch & 1;
#pragma unroll
        for (int p = 0; p < 4; p++)
            *(float4*)&hsm[buf][(p * 16 + lk) * HS_P + lf * 4] = st[p];
        __syncthreads();
        if (ch < 15) {
#pragma unroll
            for (int p = 0; p < 4; p++) {
                int k = (ch + 1) * 64 + p * 16 + lk;
                st[p] = __ldcg((const float4*)&d_hsJ[((size_t)k * Tt + t) * 64 + lf * 4]);
            }
        }
#pragma unroll
        for (int k8 = 0; k8 < 8; k8++) {
            const int kg = ch * 8 + k8;
            const int kl = k8 * 8;
            float4 af1 = __ldg(&Af1[kg * 32]);
            float4 af2 = __ldg(&Af2[kg * 32]);
#pragma unroll
            for (int nbq = 0; nbq < 8; nbq++) {
                unsigned b0 = tf32r(hsm[buf][(kl + tig) * HS_P + nbq * 8 + g]);
                unsigned b1 = tf32r(hsm[buf][(kl + tig + 4) * HS_P + nbq * 8 + g]);
                MMA_TF32(acc[0][nbq], __float_as_uint(af1.x), __float_as_uint(af1.y),
                         __float_as_uint(af1.z), __float_as_uint(af1.w), b0, b1);
                MMA_TF32(acc[1][nbq], __float_as_uint(af2.x), __float_as_uint(af2.y),
                         __float_as_uint(af2.z), __float_as_uint(af2.w), b0, b1);
            }
        }
        __syncthreads();
    }

#pragma unroll
    for (int sh = 0; sh < 2; sh++) {
        int dbase = (sh ? (w + 8) : w) * 16;
        int d1 = dbase + g, d2 = d1 + 8;
#pragma unroll
        for (int nbq = 0; nbq < 8; nbq++) {
            int bcol = nbq * 8 + tig * 2;
            *(float2*)&d_outT[(size_t)d1 * Mm + t * 64 + bcol] =
                make_float2(acc[sh][nbq][0], acc[sh][nbq][1]);
            *(float2*)&d_outT[(size_t)d2 * Mm + t * 64 + bcol] =
                make_float2(acc[sh][nbq][2], acc[sh][nbq][3]);
        }
    }
}

// ---------------- hidden = tanh(hs), [j][m'] -> [b][t][j] ----------------------
__global__ void tanhT_k(float* __restrict__ outH)
{
    __shared__ float tile[32][33];
    int m0 = blockIdx.x * 32;
    int j0 = blockIdx.y * 32;
    int tx = threadIdx.x, ty = threadIdx.y;
#pragma unroll
    for (int i = 0; i < 32; i += 8)
        tile[ty + i][tx] = d_hsJ[(size_t)(j0 + ty + i) * Mm + m0 + tx];
    __syncthreads();
    int t0 = m0 >> 6;
    int bbase = m0 & 63;
#pragma unroll
    for (int i = 0; i < 32; i += 8) {
        int mp = ty + i;
        int b = bbase + mp;
        outH[((size_t)b * Tt + t0) * Hh + j0 + tx] = tanh_ap(tile[tx][mp]);
    }
}

// ---------------- out = outT^T + bias: [d][m'] -> [b][t][d] ---------------------
__global__ void outT_k(const float* __restrict__ bo, float* __restrict__ outp)
{
    __shared__ float tile[32][33];
    int m0 = blockIdx.x * 32;
    int d0 = blockIdx.y * 32;
    int tx = threadIdx.x, ty = threadIdx.y;
#pragma unroll
    for (int i = 0; i < 32; i += 8)
        tile[ty + i][tx] = d_outT[(size_t)(d0 + ty + i) * Mm + m0 + tx];
    __syncthreads();
    int t0 = m0 >> 6;
    int bbase = m0 & 63;
    float bv = bo[d0 + tx];
#pragma unroll
    for (int i = 0; i < 32; i += 8) {
        int b = bbase + ty + i;
        outp[((size_t)b * Tt + t0) * Dd + d0 + tx] = tile[tx][ty + i] + bv;
    }
}

// ---------------- launch --------------------------------------------------------
extern "C" void kernel_launch(void* const* d_in, const int* in_sizes, int n_in,
                              void* d_out, int out_size)
{
    (void)in_sizes; (void)n_in; (void)out_size;
    const float* inp = (const float*)d_in[0];
    const float* Wx  = (const float*)d_in[1];
    const float* bx  = (const float*)d_in[2];
    const float* Wh  = (const float*)d_in[3];
    const float* bh  = (const float*)d_in[4];
    const float* Wo  = (const float*)d_in[5];
    const float* bo  = (const float*)d_in[6];
    float* out = (float*)d_out;
    float* outHidden = out + (size_t)Bb * Tt * Dd;

    const int xg_smem = 2 * 64 * XP * sizeof(float);   // 133,120 B
    cudaFuncSetAttribute(gemm_xg_mma,
                         cudaFuncAttributeMaxDynamicSharedMemorySize, xg_smem);

    init_k<<<256, 256>>>();                                  // #1 (also resets barrier)
    pack_all<<<3328, 256>>>(Wh, Wx, Wo);                     // #2
    gemm_xg_mma<<<dim3(32, 4), 256, xg_smem>>>(inp, bx, bh); // #3
    lstm_mma<<<NCTA, 256>>>();                               // #4 -> profiled
    gemm_out_mma<<<Tt, 256>>>();                             // #5
    tanhT_k<<<dim3(Mm / 32, Hh / 32), dim3(32, 8)>>>(outHidden);
    outT_k<<<dim3(Mm / 32, Dd / 32), dim3(32, 8)>>>(bo, out);
}

// round 11
// speedup vs baseline: 2.3623x; 1.1805x over previous
#include <cuda_runtime.h>
#include <cuda_fp16.h>
#include <math.h>

// Problem dims
#define Bb   64
#define Tt   512
#define Dd   256
#define Hh   1024
#define Gg   4096          // 4*H
#define Mm   32768         // B*T
#define NCTA 128

// ---------------- scratch (__device__ globals; no dynamic allocation) ----------
__device__ float d_xg[(size_t)Tt * Gg * Bb];      // [t][m=j*4+g][b]   512 MB
__device__ uint4 d_Afh[(size_t)NCTA * 2 * 64 * 32]; // Wh fp16 A-frags, 8 MB
__device__ float d_Axf[(size_t)Gg * Dd];          // Wx tf32 A-fragments, 4 MB
__device__ float d_Wof[(size_t)Dd * Hh];          // Wout tf32 A-fragments, 1 MB
__device__ float d_hsJ[(size_t)Hh * Mm];          // [j][m'] , m'=t*64+b   128 MB
__device__ float d_outT[(size_t)Dd * Mm];         // out head, [d][m']     32 MB
__device__ unsigned d_h2h[2 * 512 * Bb];          // double-buffered h, half2 [buf][k/2][b]
__device__ unsigned d_bcount;

__device__ __forceinline__ unsigned tf32r(float x)
{
    unsigned u;
    asm("cvt.rna.tf32.f32 %0, %1;" : "=r"(u) : "f"(x));
    return u;
}
__device__ __forceinline__ float tf32f(float x) { return __uint_as_float(tf32r(x)); }
__device__ __forceinline__ float tanh_ap(float x)
{
    float y;
    asm("tanh.approx.f32 %0, %1;" : "=f"(y) : "f"(x));
    return y;
}
__device__ __forceinline__ unsigned pkh2(float lo, float hi)
{
    __half2 h = __floats2half2_rn(lo, hi);
    return *(unsigned*)&h;
}

// tf32 mma: D(m16n8) += A(m16k8) * B(k8n8)
#define MMA_TF32(d, a0, a1, a2, a3, b0, b1)                                     \
    asm volatile("mma.sync.aligned.m16n8k8.row.col.f32.tf32.tf32.f32 "          \
                 "{%0,%1,%2,%3}, {%4,%5,%6,%7}, {%8,%9}, {%0,%1,%2,%3};"        \
                 : "+f"(d[0]), "+f"(d[1]), "+f"(d[2]), "+f"(d[3])               \
                 : "r"(a0), "r"(a1), "r"(a2), "r"(a3), "r"(b0), "r"(b1))

// fp16 mma: D(m16n8) += A(m16k16) * B(k16n8), fp32 accum
#define MMA_F16(d, a0, a1, a2, a3, b0, b1)                                      \
    asm volatile("mma.sync.aligned.m16n8k16.row.col.f32.f16.f16.f32 "           \
                 "{%0,%1,%2,%3}, {%4,%5,%6,%7}, {%8,%9}, {%0,%1,%2,%3};"        \
                 : "+f"(d[0]), "+f"(d[1]), "+f"(d[2]), "+f"(d[3])               \
                 : "r"(a0), "r"(a1), "r"(a2), "r"(a3), "r"(b0), "r"(b1))

// ---------------- init: zero h state, reset barrier -----------------------------
__global__ void init_k()
{
    int i = blockIdx.x * blockDim.x + threadIdx.x;
    if (i < 2 * 512 * Bb) d_h2h[i] = 0u;
    if (i == 0) d_bcount = 0u;
}

// ---------------- combined weight-fragment packing ------------------------------
// blocks [0,2048): Wh fp16   [2048,3072): Wx tf32   [3072,3328): Wout tf32
__global__ void pack_all(const float* __restrict__ Wh, const float* __restrict__ Wx,
                         const float* __restrict__ Wo)
{
    int blk = blockIdx.x;
    if (blk < 2048) {
        // fp16 A frag (m16n8k16): uint4 i = ((cb*2+ms)*64 + k16)*32 + lane
        size_t i = (size_t)blk * 256 + threadIdx.x;   // 524,288 total
        int lane = i & 31;
        int k16  = (i >> 5) & 63;
        int ms   = (i >> 11) & 1;
        int cb   = (int)(i >> 12);
        int g = lane >> 2, tig = lane & 3;
        int m1 = ms * 16 + g, m2 = m1 + 8;
        int r1 = (m1 & 3) * Hh + cb * 8 + (m1 >> 2);
        int r2 = (m2 & 3) * Hh + cb * 8 + (m2 >> 2);
        int k0 = k16 * 16 + tig * 2;
        uint4 v;
        v.x = pkh2(Wh[(size_t)r1 * Hh + k0],     Wh[(size_t)r1 * Hh + k0 + 1]);
        v.y = pkh2(Wh[(size_t)r2 * Hh + k0],     Wh[(size_t)r2 * Hh + k0 + 1]);
        v.z = pkh2(Wh[(size_t)r1 * Hh + k0 + 8], Wh[(size_t)r1 * Hh + k0 + 9]);
        v.w = pkh2(Wh[(size_t)r2 * Hh + k0 + 8], Wh[(size_t)r2 * Hh + k0 + 9]);
        d_Afh[i] = v;
    } else if (blk < 3072) {
        size_t i = (size_t)(blk - 2048) * 256 + threadIdx.x;
        int lane = i & 31;
        int k8   = (i >> 5) & 31;
        int ws   = (i >> 10) & 7;
        int gb   = (int)(i >> 13);
        int g = lane >> 2, tig = lane & 3;
        int m1 = gb * 128 + ws * 16 + g;
        int m2 = m1 + 8;
        int r1 = (m1 & 3) * Hh + (m1 >> 2);
        int r2 = (m2 & 3) * Hh + (m2 >> 2);
        int k0 = k8 * 8;
        float4 v;
        v.x = __uint_as_float(tf32r(Wx[(size_t)r1 * Dd + k0 + tig]));
        v.y = __uint_as_float(tf32r(Wx[(size_t)r2 * Dd + k0 + tig]));
        v.z = __uint_as_float(tf32r(Wx[(size_t)r1 * Dd + k0 + tig + 4]));
        v.w = __uint_as_float(tf32r(Wx[(size_t)r2 * Dd + k0 + tig + 4]));
        ((float4*)d_Axf)[i] = v;
    } else {
        size_t i = (size_t)(blk - 3072) * 256 + threadIdx.x;
        int lane = i & 31;
        int k8   = (i >> 5) & 127;
        int s    = (int)(i >> 12);
        int g = lane >> 2, tig = lane & 3;
        int d1 = s * 16 + g, d2 = d1 + 8;
        int k0 = k8 * 8;
        float4 v;
        v.x = __uint_as_float(tf32r(Wo[(size_t)d1 * Hh + k0 + tig]));
        v.y = __uint_as_float(tf32r(Wo[(size_t)d2 * Hh + k0 + tig]));
        v.z = __uint_as_float(tf32r(Wo[(size_t)d1 * Hh + k0 + tig + 4]));
        v.w = __uint_as_float(tf32r(Wo[(size_t)d2 * Hh + k0 + tig + 4]));
        ((float4*)d_Wof)[i] = v;
    }
}

// ---------------- GEMM 1 (tf32 mma): xg[t][m][b] = inputs . Wx^T + bx + bh ------
#define XP 260
__global__ void __launch_bounds__(256) gemm_xg_mma(
    const float* __restrict__ inp, const float* __restrict__ bx,
    const float* __restrict__ bh)
{
    extern __shared__ float Bsm[];            // 2 * 64 * XP floats
    const int tid = threadIdx.x, w = tid >> 5, lane = tid & 31;
    const int g = lane >> 2, tig = lane & 3;
    const int gb = blockIdx.x;
    const int m1 = gb * 128 + w * 16 + g, m2 = m1 + 8;
    const int r1 = (m1 & 3) * Hh + (m1 >> 2), r2 = (m2 & 3) * Hh + (m2 >> 2);
    const float bias1 = bx[r1] + bh[r1];
    const float bias2 = bx[r2] + bh[r2];
    const float4* Af = (const float4*)d_Axf + (size_t)(gb * 8 + w) * 1024 + lane;
    const int brow = w * 8 + (lane >> 2);
    const int bq = lane & 3;

    for (int t0 = blockIdx.y * 2; t0 < Tt; t0 += 8) {
#pragma unroll
        for (int sl = 0; sl < 2; sl++) {
            const float4* src = (const float4*)(inp + ((size_t)brow * Tt + t0 + sl) * Dd);
            float* dst = Bsm + sl * 64 * XP + brow * XP;
#pragma unroll
            for (int i2 = 0; i2 < 16; i2++) {
                float4 v = __ldg(&src[i2 * 4 + bq]);
                v.x = tf32f(v.x); v.y = tf32f(v.y);
                v.z = tf32f(v.z); v.w = tf32f(v.w);
                *(float4*)&dst[(i2 * 4 + bq) * 4] = v;
            }
        }
        __syncthreads();

        float acc[2][8][4];
#pragma unroll
        for (int sl = 0; sl < 2; sl++)
#pragma unroll
            for (int nb = 0; nb < 8; nb++)
#pragma unroll
                for (int q = 0; q < 4; q++) acc[sl][nb][q] = 0.f;

#pragma unroll 4
        for (int k8 = 0; k8 < 32; k8++) {
            float4 a4 = __ldg(&Af[k8 * 32]);
            unsigned a0 = __float_as_uint(a4.x), a1 = __float_as_uint(a4.y);
            unsigned a2 = __float_as_uint(a4.z), a3 = __float_as_uint(a4.w);
            const int kl = k8 * 8;
#pragma unroll
            for (int nb = 0; nb < 8; nb++) {
#pragma unroll
                for (int sl = 0; sl < 2; sl++) {
                    const float* bp = Bsm + sl * 64 * XP + (nb * 8 + g) * XP + kl + tig;
                    unsigned b0 = __float_as_uint(bp[0]);
                    unsigned b1 = __float_as_uint(bp[4]);
                    MMA_TF32(acc[sl][nb], a0, a1, a2, a3, b0, b1);
                }
            }
        }
#pragma unroll
        for (int sl = 0; sl < 2; sl++) {
            int t = t0 + sl;
#pragma unroll
            for (int nb = 0; nb < 8; nb++) {
                *(float2*)&d_xg[((size_t)t * Gg + m1) * 64 + nb * 8 + tig * 2] =
                    make_float2(acc[sl][nb][0] + bias1, acc[sl][nb][1] + bias1);
                *(float2*)&d_xg[((size_t)t * Gg + m2) * 64 + nb * 8 + tig * 2] =
                    make_float2(acc[sl][nb][2] + bias2, acc[sl][nb][3] + bias2);
            }
        }
        __syncthreads();
    }
}

// ---------------- software grid barrier (monotonic counter, acq/rel) ------------
__device__ __forceinline__ void grid_sync(unsigned target)
{
    __syncthreads();
    if (threadIdx.x == 0) {
        asm volatile("red.release.gpu.global.add.u32 [%0], 1;"
                     :: "l"(&d_bcount) : "memory");
        unsigned c;
        do {
            asm volatile("ld.acquire.gpu.global.u32 %0, [%1];"
                         : "=r"(c) : "l"(&d_bcount) : "memory");
        } while (c < target);
    }
    __syncthreads();
}

__device__ __forceinline__ float sigm(float x) { return 1.0f / (1.0f + expf(-x)); }

// ---------------- persistent LSTM recurrence (fp16 mma, 16 warps split-K) -------
// 128 CTAs x 512 thr.  CTA owns 32 gate-cols, N=64, K=1024.
// Warp w: kh = w>>3 (k-half), ms = w&1 (m-strip), n0 = ((w>>1)&3)*16.
// Each k-half stages its own h range in 8 double-buffered k=64 chunks
// (32 half2-rows x 64 words, pitch 72 -> B-frag banks 8*tig+g, conflict-free).
// Two D buffers (one per half) summed in the pointwise.  ONE barrier per step.
#define HP2 72
#define DS_P 68
#define HS2_SZ (2 * 2 * 32 * HP2)            // unsigned words
#define DS_SZ  (2 * 32 * DS_P)               // floats
__global__ void __launch_bounds__(512, 1) lstm_mma()
{
    extern __shared__ __align__(16) unsigned smem_u[];
    unsigned* hs2 = smem_u;                          // [kh*2+buf][32*HP2]
    float*    Ds  = (float*)(smem_u + HS2_SZ);       // [kh][32*DS_P]
    float*    hnS = Ds + DS_SZ;                      // [8][64]

    const int tid  = threadIdx.x;
    const int cta  = blockIdx.x;
    const int w    = tid >> 5, lane = tid & 31;
    const int g    = lane >> 2, tig = lane & 3;
    const int kh   = w >> 3;
    const int ms   = w & 1;
    const int n0   = ((w >> 1) & 3) * 16;
    const int lt   = tid & 255;          // staging index within half
    const int pb   = tid & 63;           // pointwise batch
    const int jl   = tid >> 6;           // pointwise local j (0..7)
    const uint4* Af = d_Afh + ((size_t)cta * 2 + ms) * 64 * 32 + kh * 32 * 32 + lane;
    float cs = 0.f;

    for (int t = 0; t < Tt; t++) {
        const unsigned* hcur = d_h2h + (size_t)(t & 1) * (512 * Bb) + kh * 256 * Bb;
        unsigned*       hnxt = d_h2h + (size_t)((t + 1) & 1) * (512 * Bb);

        // prefetch xg for this thread's (jl, pb) (DRAM latency hidden)
        float xg0[4];
#pragma unroll
        for (int q = 0; q < 4; q++)
            xg0[q] = d_xg[(((size_t)t * Hh + cta * 8 + jl) * 4 + q) * Bb + pb];

        float acc0[4] = {0.f, 0.f, 0.f, 0.f};
        float acc1[4] = {0.f, 0.f, 0.f, 0.f};

        // preload chunk 0 of this half: 512 uint4, 256 threads x 2
        uint4 st[2];
#pragma unroll
        for (int p = 0; p < 2; p++)
            st[p] = __ldcg((const uint4*)hcur + p * 256 + lt);

#pragma unroll 1
        for (int ch = 0; ch < 8; ch++) {
            const int buf = ch & 1;
            unsigned* hb = hs2 + (kh * 2 + buf) * (32 * HP2);
#pragma unroll
            for (int p = 0; p < 2; p++) {
                int idx = p * 256 + lt;
                *(uint4*)&hb[(idx >> 4) * HP2 + (idx & 15) * 4] = st[p];
            }
            __syncthreads();
            if (ch < 7) {
#pragma unroll
                for (int p = 0; p < 2; p++)
                    st[p] = __ldcg((const uint4*)hcur + (ch + 1) * 512 + p * 256 + lt);
            }
#pragma unroll
            for (int k16 = 0; k16 < 4; k16++) {
                uint4 a4 = __ldg(&Af[(ch * 4 + k16) * 32]);
                const int kb = k16 * 8;
                unsigned b0 = hb[(kb + tig) * HP2 + n0 + g];
                unsigned b1 = hb[(kb + tig + 4) * HP2 + n0 + g];
                unsigned b2 = hb[(kb + tig) * HP2 + n0 + 8 + g];
                unsigned b3 = hb[(kb + tig + 4) * HP2 + n0 + 8 + g];
                MMA_F16(acc0, a4.x, a4.y, a4.z, a4.w, b0, b1);
                MMA_F16(acc1, a4.x, a4.y, a4.z, a4.w, b2, b3);
            }
        }

        // D fragments -> per-half smem buffer
        {
            float* D = Ds + kh * (32 * DS_P);
            int r1 = ms * 16 + g, r2 = r1 + 8;
            *(float2*)&D[r1 * DS_P + n0 + tig * 2]     = make_float2(acc0[0], acc0[1]);
            *(float2*)&D[r2 * DS_P + n0 + tig * 2]     = make_float2(acc0[2], acc0[3]);
            *(float2*)&D[r1 * DS_P + n0 + 8 + tig * 2] = make_float2(acc1[0], acc1[1]);
            *(float2*)&D[r2 * DS_P + n0 + 8 + tig * 2] = make_float2(acc1[2], acc1[3]);
        }
        __syncthreads();

        // pointwise: one (jl, pb) per thread; sum the two k-half D buffers
        {
            float gi = Ds[(jl * 4 + 0) * DS_P + pb] + Ds[DS_SZ / 2 + (jl * 4 + 0) * DS_P + pb] + xg0[0];
            float gf = Ds[(jl * 4 + 1) * DS_P + pb] + Ds[DS_SZ / 2 + (jl * 4 + 1) * DS_P + pb] + xg0[1];
            float gg = Ds[(jl * 4 + 2) * DS_P + pb] + Ds[DS_SZ / 2 + (jl * 4 + 2) * DS_P + pb] + xg0[2];
            float go = Ds[(jl * 4 + 3) * DS_P + pb] + Ds[DS_SZ / 2 + (jl * 4 + 3) * DS_P + pb] + xg0[3];
            float si = sigm(gi), sf = sigm(gf), sg = sigm(gg), so = sigm(go);
            float cn = cs * sf + si * sg;        // NOTE: sigmoid cell gate (per ref)
            cs = cn;
            float hn = so * tanhf(cn);
            int j = cta * 8 + jl;
            d_hsJ[((size_t)j * Tt + t) * 64 + pb] = hn;
            hnS[jl * 64 + pb] = hn;
        }
        __syncthreads();
        if (tid < 256) {
            int jp = tid >> 6, b = tid & 63;
            __stcg(&hnxt[(cta * 4 + jp) * 64 + b],
                   pkh2(hnS[(2 * jp) * 64 + b], hnS[(2 * jp + 1) * 64 + b]));
        }
        grid_sync((unsigned)NCTA * (t + 1));
    }
}

// ---------------- GEMM 3 (tf32 mma): outT[d][m'] = Wout . hs --------------------
#define HS_P 72
__global__ void __launch_bounds__(256) gemm_out_mma()
{
    __shared__ __align__(16) float hsm[2][64 * HS_P];
    const int tid = threadIdx.x, w = tid >> 5, lane = tid & 31;
    const int g = lane >> 2, tig = lane & 3;
    const int t = blockIdx.x;
    const int lk = tid >> 4, lf = tid & 15;
    const float4* Af1 = (const float4*)d_Wof + (size_t)w * 128 * 32 + lane;
    const float4* Af2 = (const float4*)d_Wof + (size_t)(w + 8) * 128 * 32 + lane;

    float acc[2][8][4];
#pragma unroll
    for (int sh = 0; sh < 2; sh++)
#pragma unroll
        for (int nbq = 0; nbq < 8; nbq++)
#pragma unroll
            for (int q = 0; q < 4; q++) acc[sh][nbq][q] = 0.f;

    float4 st[4];
#pragma unroll
    for (int p = 0; p < 4; p++) {
        int k = p * 16 + lk;
        st[p] = __ldcg((const float4*)&d_hsJ[((size_t)k * Tt + t) * 64 + lf * 4]);
    }

#pragma unroll 1
    for (int ch = 0; ch < 16; ch++) {
        const int buf = ch & 1;
#pragma unroll
        for (int p = 0; p < 4; p++)
            *(float4*)&hsm[buf][(p * 16 + lk) * HS_P + lf * 4] = st[p];
        __syncthreads();
        if (ch < 15) {
#pragma unroll
            for (int p = 0; p < 4; p++) {
                int k = (ch + 1) * 64 + p * 16 + lk;
                st[p] = __ldcg((const float4*)&d_hsJ[((size_t)k * Tt + t) * 64 + lf * 4]);
            }
        }
#pragma unroll
        for (int k8 = 0; k8 < 8; k8++) {
            const int kg = ch * 8 + k8;
            const int kl = k8 * 8;
            float4 af1 = __ldg(&Af1[kg * 32]);
            float4 af2 = __ldg(&Af2[kg * 32]);
#pragma unroll
            for (int nbq = 0; nbq < 8; nbq++) {
                unsigned b0 = tf32r(hsm[buf][(kl + tig) * HS_P + nbq * 8 + g]);
                unsigned b1 = tf32r(hsm[buf][(kl + tig + 4) * HS_P + nbq * 8 + g]);
                MMA_TF32(acc[0][nbq], __float_as_uint(af1.x), __float_as_uint(af1.y),
                         __float_as_uint(af1.z), __float_as_uint(af1.w), b0, b1);
                MMA_TF32(acc[1][nbq], __float_as_uint(af2.x), __float_as_uint(af2.y),
                         __float_as_uint(af2.z), __float_as_uint(af2.w), b0, b1);
            }
        }
        __syncthreads();
    }

#pragma unroll
    for (int sh = 0; sh < 2; sh++) {
        int dbase = (sh ? (w + 8) : w) * 16;
        int d1 = dbase + g, d2 = d1 + 8;
#pragma unroll
        for (int nbq = 0; nbq < 8; nbq++) {
            int bcol = nbq * 8 + tig * 2;
            *(float2*)&d_outT[(size_t)d1 * Mm + t * 64 + bcol] =
                make_float2(acc[sh][nbq][0], acc[sh][nbq][1]);
            *(float2*)&d_outT[(size_t)d2 * Mm + t * 64 + bcol] =
                make_float2(acc[sh][nbq][2], acc[sh][nbq][3]);
        }
    }
}

// ---------------- hidden = tanh(hs), [j][m'] -> [b][t][j] ----------------------
__global__ void tanhT_k(float* __restrict__ outH)
{
    __shared__ float tile[32][33];
    int m0 = blockIdx.x * 32;
    int j0 = blockIdx.y * 32;
    int tx = threadIdx.x, ty = threadIdx.y;
#pragma unroll
    for (int i = 0; i < 32; i += 8)
        tile[ty + i][tx] = d_hsJ[(size_t)(j0 + ty + i) * Mm + m0 + tx];
    __syncthreads();
    int t0 = m0 >> 6;
    int bbase = m0 & 63;
#pragma unroll
    for (int i = 0; i < 32; i += 8) {
        int mp = ty + i;
        int b = bbase + mp;
        outH[((size_t)b * Tt + t0) * Hh + j0 + tx] = tanh_ap(tile[tx][mp]);
    }
}

// ---------------- out = outT^T + bias: [d][m'] -> [b][t][d] ---------------------
__global__ void outT_k(const float* __restrict__ bo, float* __restrict__ outp)
{
    __shared__ float tile[32][33];
    int m0 = blockIdx.x * 32;
    int d0 = blockIdx.y * 32;
    int tx = threadIdx.x, ty = threadIdx.y;
#pragma unroll
    for (int i = 0; i < 32; i += 8)
        tile[ty + i][tx] = d_outT[(size_t)(d0 + ty + i) * Mm + m0 + tx];
    __syncthreads();
    int t0 = m0 >> 6;
    int bbase = m0 & 63;
    float bv = bo[d0 + tx];
#pragma unroll
    for (int i = 0; i < 32; i += 8) {
        int b = bbase + ty + i;
        outp[((size_t)b * Tt + t0) * Dd + d0 + tx] = tile[tx][ty + i] + bv;
    }
}

// ---------------- launch --------------------------------------------------------
extern "C" void kernel_launch(void* const* d_in, const int* in_sizes, int n_in,
                              void* d_out, int out_size)
{
    (void)in_sizes; (void)n_in; (void)out_size;
    const float* inp = (const float*)d_in[0];
    const float* Wx  = (const float*)d_in[1];
    const float* bx  = (const float*)d_in[2];
    const float* Wh  = (const float*)d_in[3];
    const float* bh  = (const float*)d_in[4];
    const float* Wo  = (const float*)d_in[5];
    const float* bo  = (const float*)d_in[6];
    float* out = (float*)d_out;
    float* outHidden = out + (size_t)Bb * Tt * Dd;

    const int xg_smem = 2 * 64 * XP * sizeof(float);   // 133,120 B
    cudaFuncSetAttribute(gemm_xg_mma,
                         cudaFuncAttributeMaxDynamicSharedMemorySize, xg_smem);
    const int lstm_smem = (HS2_SZ + DS_SZ + 512) * 4;  // ~56.3 KB
    cudaFuncSetAttribute(lstm_mma,
                         cudaFuncAttributeMaxDynamicSharedMemorySize, lstm_smem);

    init_k<<<256, 256>>>();                                  // #1 (also resets barrier)
    pack_all<<<3328, 256>>>(Wh, Wx, Wo);                     // #2
    gemm_xg_mma<<<dim3(32, 4), 256, xg_smem>>>(inp, bx, bh); // #3
    lstm_mma<<<NCTA, 512, lstm_smem>>>();                    // #4 -> profiled
    gemm_out_mma<<<Tt, 256>>>();                             // #5
    tanhT_k<<<dim3(Mm / 32, Hh / 32), dim3(32, 8)>>>(outHidden);
    outT_k<<<dim3(Mm / 32, Dd / 32), dim3(32, 8)>>>(bo, out);
}

// round 12
// speedup vs baseline: 2.4841x; 1.0516x over previous
#include <cuda_runtime.h>
#include <cuda_fp16.h>
#include <math.h>

// Problem dims
#define Bb   64
#define Tt   512
#define Dd   256
#define Hh   1024
#define Gg   4096          // 4*H
#define Mm   32768         // B*T
#define NCTA 128

// ---------------- scratch (__device__ globals; no dynamic allocation) ----------
__device__ float d_xg[(size_t)Tt * Gg * Bb];      // [t][m=j*4+g][b]   512 MB
__device__ uint4 d_Afh[(size_t)NCTA * 2 * 64 * 32]; // Wh fp16 A-frags, 8 MB
__device__ float d_Axf[(size_t)Gg * Dd];          // Wx tf32 A-fragments, 4 MB
__device__ float d_Wof[(size_t)Dd * Hh];          // Wout tf32 A-fragments, 1 MB
__device__ float d_hsJ[(size_t)Hh * Mm];          // [j][m'] , m'=t*64+b   128 MB
__device__ float d_outT[(size_t)Dd * Mm];         // out head, [d][m']     32 MB
__device__ unsigned d_h2h[2 * 512 * Bb];          // double-buffered h, half2 [buf][k/2][b]
__device__ unsigned d_bcount;

__device__ __forceinline__ unsigned tf32r(float x)
{
    unsigned u;
    asm("cvt.rna.tf32.f32 %0, %1;" : "=r"(u) : "f"(x));
    return u;
}
__device__ __forceinline__ float tf32f(float x) { return __uint_as_float(tf32r(x)); }
__device__ __forceinline__ float tanh_ap(float x)
{
    float y;
    asm("tanh.approx.f32 %0, %1;" : "=f"(y) : "f"(x));
    return y;
}
__device__ __forceinline__ unsigned pkh2(float lo, float hi)
{
    __half2 h = __floats2half2_rn(lo, hi);
    return *(unsigned*)&h;
}

// tf32 mma: D(m16n8) += A(m16k8) * B(k8n8)
#define MMA_TF32(d, a0, a1, a2, a3, b0, b1)                                     \
    asm volatile("mma.sync.aligned.m16n8k8.row.col.f32.tf32.tf32.f32 "          \
                 "{%0,%1,%2,%3}, {%4,%5,%6,%7}, {%8,%9}, {%0,%1,%2,%3};"        \
                 : "+f"(d[0]), "+f"(d[1]), "+f"(d[2]), "+f"(d[3])               \
                 : "r"(a0), "r"(a1), "r"(a2), "r"(a3), "r"(b0), "r"(b1))

// fp16 mma: D(m16n8) += A(m16k16) * B(k16n8), fp32 accum
#define MMA_F16(d, a0, a1, a2, a3, b0, b1)                                      \
    asm volatile("mma.sync.aligned.m16n8k16.row.col.f32.f16.f16.f32 "           \
                 "{%0,%1,%2,%3}, {%4,%5,%6,%7}, {%8,%9}, {%0,%1,%2,%3};"        \
                 : "+f"(d[0]), "+f"(d[1]), "+f"(d[2]), "+f"(d[3])               \
                 : "r"(a0), "r"(a1), "r"(a2), "r"(a3), "r"(b0), "r"(b1))

// ---------------- init: zero h state, reset barrier -----------------------------
__global__ void init_k()
{
    int i = blockIdx.x * blockDim.x + threadIdx.x;
    if (i < 2 * 512 * Bb) d_h2h[i] = 0u;
    if (i == 0) d_bcount = 0u;
}

// ---------------- combined weight-fragment packing ------------------------------
// blocks [0,2048): Wh fp16   [2048,3072): Wx tf32   [3072,3328): Wout tf32
__global__ void pack_all(const float* __restrict__ Wh, const float* __restrict__ Wx,
                         const float* __restrict__ Wo)
{
    int blk = blockIdx.x;
    if (blk < 2048) {
        // fp16 A frag (m16n8k16): uint4 i = ((cb*2+ms)*64 + k16)*32 + lane
        size_t i = (size_t)blk * 256 + threadIdx.x;   // 524,288 total
        int lane = i & 31;
        int k16  = (i >> 5) & 63;
        int ms   = (i >> 11) & 1;
        int cb   = (int)(i >> 12);
        int g = lane >> 2, tig = lane & 3;
        int m1 = ms * 16 + g, m2 = m1 + 8;
        int r1 = (m1 & 3) * Hh + cb * 8 + (m1 >> 2);
        int r2 = (m2 & 3) * Hh + cb * 8 + (m2 >> 2);
        int k0 = k16 * 16 + tig * 2;
        uint4 v;
        v.x = pkh2(Wh[(size_t)r1 * Hh + k0],     Wh[(size_t)r1 * Hh + k0 + 1]);
        v.y = pkh2(Wh[(size_t)r2 * Hh + k0],     Wh[(size_t)r2 * Hh + k0 + 1]);
        v.z = pkh2(Wh[(size_t)r1 * Hh + k0 + 8], Wh[(size_t)r1 * Hh + k0 + 9]);
        v.w = pkh2(Wh[(size_t)r2 * Hh + k0 + 8], Wh[(size_t)r2 * Hh + k0 + 9]);
        d_Afh[i] = v;
    } else if (blk < 3072) {
        size_t i = (size_t)(blk - 2048) * 256 + threadIdx.x;
        int lane = i & 31;
        int k8   = (i >> 5) & 31;
        int ws   = (i >> 10) & 7;
        int gb   = (int)(i >> 13);
        int g = lane >> 2, tig = lane & 3;
        int m1 = gb * 128 + ws * 16 + g;
        int m2 = m1 + 8;
        int r1 = (m1 & 3) * Hh + (m1 >> 2);
        int r2 = (m2 & 3) * Hh + (m2 >> 2);
        int k0 = k8 * 8;
        float4 v;
        v.x = __uint_as_float(tf32r(Wx[(size_t)r1 * Dd + k0 + tig]));
        v.y = __uint_as_float(tf32r(Wx[(size_t)r2 * Dd + k0 + tig]));
        v.z = __uint_as_float(tf32r(Wx[(size_t)r1 * Dd + k0 + tig + 4]));
        v.w = __uint_as_float(tf32r(Wx[(size_t)r2 * Dd + k0 + tig + 4]));
        ((float4*)d_Axf)[i] = v;
    } else {
        size_t i = (size_t)(blk - 3072) * 256 + threadIdx.x;
        int lane = i & 31;
        int k8   = (i >> 5) & 127;
        int s    = (int)(i >> 12);
        int g = lane >> 2, tig = lane & 3;
        int d1 = s * 16 + g, d2 = d1 + 8;
        int k0 = k8 * 8;
        float4 v;
        v.x = __uint_as_float(tf32r(Wo[(size_t)d1 * Hh + k0 + tig]));
        v.y = __uint_as_float(tf32r(Wo[(size_t)d2 * Hh + k0 + tig]));
        v.z = __uint_as_float(tf32r(Wo[(size_t)d1 * Hh + k0 + tig + 4]));
        v.w = __uint_as_float(tf32r(Wo[(size_t)d2 * Hh + k0 + tig + 4]));
        ((float4*)d_Wof)[i] = v;
    }
}

// ---------------- GEMM 1 (tf32 mma): xg[t][m][b] = inputs . Wx^T + bx + bh ------
#define XP 260
__global__ void __launch_bounds__(256) gemm_xg_mma(
    const float* __restrict__ inp, const float* __restrict__ bx,
    const float* __restrict__ bh)
{
    extern __shared__ float Bsm[];            // 2 * 64 * XP floats
    const int tid = threadIdx.x, w = tid >> 5, lane = tid & 31;
    const int g = lane >> 2, tig = lane & 3;
    const int gb = blockIdx.x;
    const int m1 = gb * 128 + w * 16 + g, m2 = m1 + 8;
    const int r1 = (m1 & 3) * Hh + (m1 >> 2), r2 = (m2 & 3) * Hh + (m2 >> 2);
    const float bias1 = bx[r1] + bh[r1];
    const float bias2 = bx[r2] + bh[r2];
    const float4* Af = (const float4*)d_Axf + (size_t)(gb * 8 + w) * 1024 + lane;
    const int brow = w * 8 + (lane >> 2);
    const int bq = lane & 3;

    for (int t0 = blockIdx.y * 2; t0 < Tt; t0 += 8) {
#pragma unroll
        for (int sl = 0; sl < 2; sl++) {
            const float4* src = (const float4*)(inp + ((size_t)brow * Tt + t0 + sl) * Dd);
            float* dst = Bsm + sl * 64 * XP + brow * XP;
#pragma unroll
            for (int i2 = 0; i2 < 16; i2++) {
                float4 v = __ldg(&src[i2 * 4 + bq]);
                v.x = tf32f(v.x); v.y = tf32f(v.y);
                v.z = tf32f(v.z); v.w = tf32f(v.w);
                *(float4*)&dst[(i2 * 4 + bq) * 4] = v;
            }
        }
        __syncthreads();

        float acc[2][8][4];
#pragma unroll
        for (int sl = 0; sl < 2; sl++)
#pragma unroll
            for (int nb = 0; nb < 8; nb++)
#pragma unroll
                for (int q = 0; q < 4; q++) acc[sl][nb][q] = 0.f;

#pragma unroll 4
        for (int k8 = 0; k8 < 32; k8++) {
            float4 a4 = __ldg(&Af[k8 * 32]);
            unsigned a0 = __float_as_uint(a4.x), a1 = __float_as_uint(a4.y);
            unsigned a2 = __float_as_uint(a4.z), a3 = __float_as_uint(a4.w);
            const int kl = k8 * 8;
#pragma unroll
            for (int nb = 0; nb < 8; nb++) {
#pragma unroll
                for (int sl = 0; sl < 2; sl++) {
                    const float* bp = Bsm + sl * 64 * XP + (nb * 8 + g) * XP + kl + tig;
                    unsigned b0 = __float_as_uint(bp[0]);
                    unsigned b1 = __float_as_uint(bp[4]);
                    MMA_TF32(acc[sl][nb], a0, a1, a2, a3, b0, b1);
                }
            }
        }
#pragma unroll
        for (int sl = 0; sl < 2; sl++) {
            int t = t0 + sl;
#pragma unroll
            for (int nb = 0; nb < 8; nb++) {
                *(float2*)&d_xg[((size_t)t * Gg + m1) * 64 + nb * 8 + tig * 2] =
                    make_float2(acc[sl][nb][0] + bias1, acc[sl][nb][1] + bias1);
                *(float2*)&d_xg[((size_t)t * Gg + m2) * 64 + nb * 8 + tig * 2] =
                    make_float2(acc[sl][nb][2] + bias2, acc[sl][nb][3] + bias2);
            }
        }
        __syncthreads();
    }
}

// ---------------- software grid barrier (monotonic counter, acq/rel) ------------
__device__ __forceinline__ void grid_sync(unsigned target)
{
    __syncthreads();
    if (threadIdx.x == 0) {
        asm volatile("red.release.gpu.global.add.u32 [%0], 1;"
                     :: "l"(&d_bcount) : "memory");
        unsigned c;
        do {
            asm volatile("ld.acquire.gpu.global.u32 %0, [%1];"
                         : "=r"(c) : "l"(&d_bcount) : "memory");
        } while (c < target);
    }
    __syncthreads();
}

__device__ __forceinline__ float sigm(float x) { return 1.0f / (1.0f + expf(-x)); }

// ---------------- persistent LSTM recurrence (fp16 mma, full-h staging) ---------
// 128 CTAs x 512 thr (16 warps).  CTA owns 32 gate-cols, N=64, K=1024.
// Per step: stage ENTIRE h (512 half2-rows x 64 words, pitch 72, 144 KB) with
// ONE sync, then each warp streams its 32 k16 MMAs with no further syncs.
// Warp w: kh = w>>3 (k-half), ms = w&1 (m-strip), n0 = ((w>>1)&3)*16.
// Two D buffers (one per k-half) summed in the pointwise.  3 CTA syncs + 1
// grid barrier per step.  xg for t+1 prefetched before the grid barrier.
#define HP2 72
#define HS_FULL (512 * HP2)                  // unsigned words (144 KB)
#define DS_P 68
#define DS_SZ  (2 * 32 * DS_P)               // floats
__global__ void __launch_bounds__(512, 1) lstm_mma()
{
    extern __shared__ __align__(16) unsigned smem_u[];
    unsigned* hs  = smem_u;                          // [512][HP2]
    float*    Ds  = (float*)(smem_u + HS_FULL);      // [kh][32*DS_P]
    float*    hnS = Ds + DS_SZ;                      // [8][64]

    const int tid  = threadIdx.x;
    const int cta  = blockIdx.x;
    const int w    = tid >> 5, lane = tid & 31;
    const int g    = lane >> 2, tig = lane & 3;
    const int kh   = w >> 3;
    const int ms   = w & 1;
    const int n0   = ((w >> 1) & 3) * 16;
    const int pb   = tid & 63;           // pointwise batch
    const int jl   = tid >> 6;           // pointwise local j (0..7)
    const uint4* Af = d_Afh + ((size_t)(cta * 2 + ms) * 64 + kh * 32) * 32 + lane;
    float cs = 0.f;

    // prefetch xg for t = 0
    float xg0[4];
#pragma unroll
    for (int q = 0; q < 4; q++)
        xg0[q] = d_xg[(((size_t)0 * Hh + cta * 8 + jl) * 4 + q) * Bb + pb];

    for (int t = 0; t < Tt; t++) {
        const unsigned* hcur = d_h2h + (size_t)(t & 1) * (512 * Bb);
        unsigned*       hnxt = d_h2h + (size_t)((t + 1) & 1) * (512 * Bb);

        // ---- stage full h: 8192 uint4, 512 threads x 16, two MLP-8 batches ----
        {
            uint4 st[8];
#pragma unroll
            for (int p = 0; p < 8; p++)
                st[p] = __ldcg((const uint4*)hcur + p * 512 + tid);
#pragma unroll
            for (int p = 0; p < 8; p++) {
                int idx = p * 512 + tid;
                *(uint4*)&hs[(idx >> 4) * HP2 + (idx & 15) * 4] = st[p];
            }
#pragma unroll
            for (int p = 0; p < 8; p++)
                st[p] = __ldcg((const uint4*)hcur + (p + 8) * 512 + tid);
#pragma unroll
            for (int p = 0; p < 8; p++) {
                int idx = (p + 8) * 512 + tid;
                *(uint4*)&hs[(idx >> 4) * HP2 + (idx & 15) * 4] = st[p];
            }
        }
        __syncthreads();

        // ---- 32 k16 MMAs per warp, no syncs ----
        float acc0[4] = {0.f, 0.f, 0.f, 0.f};
        float acc1[4] = {0.f, 0.f, 0.f, 0.f};
#pragma unroll 8
        for (int kk = 0; kk < 32; kk++) {
            uint4 a4 = __ldg(&Af[kk * 32]);
            const int rb = (kh * 32 + kk) * 8;
            unsigned b0 = hs[(rb + tig) * HP2 + n0 + g];
            unsigned b1 = hs[(rb + tig + 4) * HP2 + n0 + g];
            unsigned b2 = hs[(rb + tig) * HP2 + n0 + 8 + g];
            unsigned b3 = hs[(rb + tig + 4) * HP2 + n0 + 8 + g];
            MMA_F16(acc0, a4.x, a4.y, a4.z, a4.w, b0, b1);
            MMA_F16(acc1, a4.x, a4.y, a4.z, a4.w, b2, b3);
        }

        // D fragments -> per-half smem buffer
        {
            float* D = Ds + kh * (32 * DS_P);
            int r1 = ms * 16 + g, r2 = r1 + 8;
            *(float2*)&D[r1 * DS_P + n0 + tig * 2]     = make_float2(acc0[0], acc0[1]);
            *(float2*)&D[r2 * DS_P + n0 + tig * 2]     = make_float2(acc0[2], acc0[3]);
            *(float2*)&D[r1 * DS_P + n0 + 8 + tig * 2] = make_float2(acc1[0], acc1[1]);
            *(float2*)&D[r2 * DS_P + n0 + 8 + tig * 2] = make_float2(acc1[2], acc1[3]);
        }
        __syncthreads();

        // pointwise: one (jl, pb) per thread; sum the two k-half D buffers
        {
            float gi = Ds[(jl * 4 + 0) * DS_P + pb] + Ds[DS_SZ / 2 + (jl * 4 + 0) * DS_P + pb] + xg0[0];
            float gf = Ds[(jl * 4 + 1) * DS_P + pb] + Ds[DS_SZ / 2 + (jl * 4 + 1) * DS_P + pb] + xg0[1];
            float gg = Ds[(jl * 4 + 2) * DS_P + pb] + Ds[DS_SZ / 2 + (jl * 4 + 2) * DS_P + pb] + xg0[2];
            float go = Ds[(jl * 4 + 3) * DS_P + pb] + Ds[DS_SZ / 2 + (jl * 4 + 3) * DS_P + pb] + xg0[3];
            float si = sigm(gi), sf = sigm(gf), sg = sigm(gg), so = sigm(go);
            float cn = cs * sf + si * sg;        // NOTE: sigmoid cell gate (per ref)
            cs = cn;
            float hn = so * tanhf(cn);
            int j = cta * 8 + jl;
            d_hsJ[((size_t)j * Tt + t) * 64 + pb] = hn;
            hnS[jl * 64 + pb] = hn;
        }
        __syncthreads();
        if (tid < 256) {
            int jp = tid >> 6, b = tid & 63;
            __stcg(&hnxt[(cta * 4 + jp) * 64 + b],
                   pkh2(hnS[(2 * jp) * 64 + b], hnS[(2 * jp + 1) * 64 + b]));
        }

        // prefetch xg for t+1 (hidden under the grid barrier wait)
        if (t + 1 < Tt) {
#pragma unroll
            for (int q = 0; q < 4; q++)
                xg0[q] = d_xg[(((size_t)(t + 1) * Hh + cta * 8 + jl) * 4 + q) * Bb + pb];
        }
        grid_sync((unsigned)NCTA * (t + 1));
    }
}

// ---------------- GEMM 3 (tf32 mma): outT[d][m'] = Wout . hs --------------------
#define HS_P 72
__global__ void __launch_bounds__(256) gemm_out_mma()
{
    __shared__ __align__(16) float hsm[2][64 * HS_P];
    const int tid = threadIdx.x, w = tid >> 5, lane = tid & 31;
    const int g = lane >> 2, tig = lane & 3;
    const int t = blockIdx.x;
    const int lk = tid >> 4, lf = tid & 15;
    const float4* Af1 = (const float4*)d_Wof + (size_t)w * 128 * 32 + lane;
    const float4* Af2 = (const float4*)d_Wof + (size_t)(w + 8) * 128 * 32 + lane;

    float acc[2][8][4];
#pragma unroll
    for (int sh = 0; sh < 2; sh++)
#pragma unroll
        for (int nbq = 0; nbq < 8; nbq++)
#pragma unroll
            for (int q = 0; q < 4; q++) acc[sh][nbq][q] = 0.f;

    float4 st[4];
#pragma unroll
    for (int p = 0; p < 4; p++) {
        int k = p * 16 + lk;
        st[p] = __ldcg((const float4*)&d_hsJ[((size_t)k * Tt + t) * 64 + lf * 4]);
    }

#pragma unroll 1
    for (int ch = 0; ch < 16; ch++) {
        const int buf = ch & 1;
#pragma unroll
        for (int p = 0; p < 4; p++)
            *(float4*)&hsm[buf][(p * 16 + lk) * HS_P + lf * 4] = st[p];
        __syncthreads();
        if (ch < 15) {
#pragma unroll
            for (int p = 0; p < 4; p++) {
                int k = (ch + 1) * 64 + p * 16 + lk;
                st[p] = __ldcg((const float4*)&d_hsJ[((size_t)k * Tt + t) * 64 + lf * 4]);
            }
        }
#pragma unroll
        for (int k8 = 0; k8 < 8; k8++) {
            const int kg = ch * 8 + k8;
            const int kl = k8 * 8;
            float4 af1 = __ldg(&Af1[kg * 32]);
            float4 af2 = __ldg(&Af2[kg * 32]);
#pragma unroll
            for (int nbq = 0; nbq < 8; nbq++) {
                unsigned b0 = tf32r(hsm[buf][(kl + tig) * HS_P + nbq * 8 + g]);
                unsigned b1 = tf32r(hsm[buf][(kl + tig + 4) * HS_P + nbq * 8 + g]);
                MMA_TF32(acc[0][nbq], __float_as_uint(af1.x), __float_as_uint(af1.y),
                         __float_as_uint(af1.z), __float_as_uint(af1.w), b0, b1);
                MMA_TF32(acc[1][nbq], __float_as_uint(af2.x), __float_as_uint(af2.y),
                         __float_as_uint(af2.z), __float_as_uint(af2.w), b0, b1);
            }
        }
        __syncthreads();
    }

#pragma unroll
    for (int sh = 0; sh < 2; sh++) {
        int dbase = (sh ? (w + 8) : w) * 16;
        int d1 = dbase + g, d2 = d1 + 8;
#pragma unroll
        for (int nbq = 0; nbq < 8; nbq++) {
            int bcol = nbq * 8 + tig * 2;
            *(float2*)&d_outT[(size_t)d1 * Mm + t * 64 + bcol] =
                make_float2(acc[sh][nbq][0], acc[sh][nbq][1]);
            *(float2*)&d_outT[(size_t)d2 * Mm + t * 64 + bcol] =
                make_float2(acc[sh][nbq][2], acc[sh][nbq][3]);
        }
    }
}

// ---------------- hidden = tanh(hs), [j][m'] -> [b][t][j] ----------------------
__global__ void tanhT_k(float* __restrict__ outH)
{
    __shared__ float tile[32][33];
    int m0 = blockIdx.x * 32;
    int j0 = blockIdx.y * 32;
    int tx = threadIdx.x, ty = threadIdx.y;
#pragma unroll
    for (int i = 0; i < 32; i += 8)
        tile[ty + i][tx] = d_hsJ[(size_t)(j0 + ty + i) * Mm + m0 + tx];
    __syncthreads();
    int t0 = m0 >> 6;
    int bbase = m0 & 63;
#pragma unroll
    for (int i = 0; i < 32; i += 8) {
        int mp = ty + i;
        int b = bbase + mp;
        outH[((size_t)b * Tt + t0) * Hh + j0 + tx] = tanh_ap(tile[tx][mp]);
    }
}

// ---------------- out = outT^T + bias: [d][m'] -> [b][t][d] ---------------------
__global__ void outT_k(const float* __restrict__ bo, float* __restrict__ outp)
{
    __shared__ float tile[32][33];
    int m0 = blockIdx.x * 32;
    int d0 = blockIdx.y * 32;
    int tx = threadIdx.x, ty = threadIdx.y;
#pragma unroll
    for (int i = 0; i < 32; i += 8)
        tile[ty + i][tx] = d_outT[(size_t)(d0 + ty + i) * Mm + m0 + tx];
    __syncthreads();
    int t0 = m0 >> 6;
    int bbase = m0 & 63;
    float bv = bo[d0 + tx];
#pragma unroll
    for (int i = 0; i < 32; i += 8) {
        int b = bbase + ty + i;
        outp[((size_t)b * Tt + t0) * Dd + d0 + tx] = tile[tx][ty + i] + bv;
    }
}

// ---------------- launch --------------------------------------------------------
extern "C" void kernel_launch(void* const* d_in, const int* in_sizes, int n_in,
                              void* d_out, int out_size)
{
    (void)in_sizes; (void)n_in; (void)out_size;
    const float* inp = (const float*)d_in[0];
    const float* Wx  = (const float*)d_in[1];
    const float* bx  = (const float*)d_in[2];
    const float* Wh  = (const float*)d_in[3];
    const float* bh  = (const float*)d_in[4];
    const float* Wo  = (const float*)d_in[5];
    const float* bo  = (const float*)d_in[6];
    float* out = (float*)d_out;
    float* outHidden = out + (size_t)Bb * Tt * Dd;

    const int xg_smem = 2 * 64 * XP * sizeof(float);   // 133,120 B
    cudaFuncSetAttribute(gemm_xg_mma,
                         cudaFuncAttributeMaxDynamicSharedMemorySize, xg_smem);
    const int lstm_smem = (HS_FULL + DS_SZ + 512) * 4; // ~166.9 KB
    cudaFuncSetAttribute(lstm_mma,
                         cudaFuncAttributeMaxDynamicSharedMemorySize, lstm_smem);

    init_k<<<256, 256>>>();                                  // #1 (also resets barrier)
    pack_all<<<3328, 256>>>(Wh, Wx, Wo);                     // #2
    gemm_xg_mma<<<dim3(32, 4), 256, xg_smem>>>(inp, bx, bh); // #3
    lstm_mma<<<NCTA, 512, lstm_smem>>>();                    // #4 -> profiled
    gemm_out_mma<<<Tt, 256>>>();                             // #5
    tanhT_k<<<dim3(Mm / 32, Hh / 32), dim3(32, 8)>>>(outHidden);
    outT_k<<<dim3(Mm / 32, Dd / 32), dim3(32, 8)>>>(bo, out);
}

// round 14
// speedup vs baseline: 2.7668x; 1.1138x over previous
#include <cuda_runtime.h>
#include <cuda_fp16.h>
#include <math.h>

// Problem dims
#define Bb   64
#define Tt   512
#define Dd   256
#define Hh   1024
#define Gg   4096          // 4*H
#define Mm   32768         // B*T
#define NCTA 128

// ---------------- scratch (__device__ globals; no dynamic allocation) ----------
__device__ float d_xg[(size_t)Tt * Gg * Bb];      // [t][m=j*4+g][b]   512 MB
__device__ uint4 d_Afh[(size_t)NCTA * 2 * 64 * 32];   // Wh fp16 A-frags, 8 MB
__device__ uint4 d_Axfh[(size_t)32 * 8 * 16 * 32];    // Wx fp16 A-frags, 2 MB
__device__ float d_Wof[(size_t)Dd * Hh];          // Wout tf32 A-fragments, 1 MB
__device__ float d_hsJ[(size_t)Hh * Mm];          // [j][m'] , m'=t*64+b   128 MB
__device__ float d_outT[(size_t)Dd * Mm];         // out head, [d][m']     32 MB
__device__ unsigned d_h2h[2 * 512 * Bb];          // double-buffered h, half2 [buf][k/2][b]
__device__ unsigned d_bcount;

__device__ __forceinline__ unsigned tf32r(float x)
{
    unsigned u;
    asm("cvt.rna.tf32.f32 %0, %1;" : "=r"(u) : "f"(x));
    return u;
}
__device__ __forceinline__ float tanh_ap(float x)
{
    float y;
    asm("tanh.approx.f32 %0, %1;" : "=f"(y) : "f"(x));
    return y;
}
__device__ __forceinline__ unsigned pkh2(float lo, float hi)
{
    __half2 h = __floats2half2_rn(lo, hi);
    return *(unsigned*)&h;
}
// fast (MUFU) sigmoid / tanh: rel err ~2^-21, negligible vs fp16-h noise
__device__ __forceinline__ float sigm(float x)
{
    return __fdividef(1.f, 1.f + __expf(-x));
}
__device__ __forceinline__ float tanh_fast(float x)
{
    return __fdividef(2.f, 1.f + __expf(-2.f * x)) - 1.f;
}

// tf32 mma: D(m16n8) += A(m16k8) * B(k8n8)
#define MMA_TF32(d, a0, a1, a2, a3, b0, b1)                                     \
    asm volatile("mma.sync.aligned.m16n8k8.row.col.f32.tf32.tf32.f32 "          \
                 "{%0,%1,%2,%3}, {%4,%5,%6,%7}, {%8,%9}, {%0,%1,%2,%3};"        \
                 : "+f"(d[0]), "+f"(d[1]), "+f"(d[2]), "+f"(d[3])               \
                 : "r"(a0), "r"(a1), "r"(a2), "r"(a3), "r"(b0), "r"(b1))

// fp16 mma: D(m16n8) += A(m16k16) * B(k16n8), fp32 accum
#define MMA_F16(d, a0, a1, a2, a3, b0, b1)                                      \
    asm volatile("mma.sync.aligned.m16n8k16.row.col.f32.f16.f16.f32 "           \
                 "{%0,%1,%2,%3}, {%4,%5,%6,%7}, {%8,%9}, {%0,%1,%2,%3};"        \
                 : "+f"(d[0]), "+f"(d[1]), "+f"(d[2]), "+f"(d[3])               \
                 : "r"(a0), "r"(a1), "r"(a2), "r"(a3), "r"(b0), "r"(b1))

// ---------------- init: zero h state, reset barrier -----------------------------
__global__ void init_k()
{
    int i = blockIdx.x * blockDim.x + threadIdx.x;
    if (i < 2 * 512 * Bb) d_h2h[i] = 0u;
    if (i == 0) d_bcount = 0u;
}

// ---------------- combined weight-fragment packing ------------------------------
// blocks [0,2048): Wh fp16   [2048,2560): Wx fp16   [2560,2816): Wout tf32
__global__ void pack_all(const float* __restrict__ Wh, const float* __restrict__ Wx,
                         const float* __restrict__ Wo)
{
    int blk = blockIdx.x;
    if (blk < 2048) {
        // Wh fp16 A frag: uint4 i = ((cb*2+ms)*64 + k16)*32 + lane
        size_t i = (size_t)blk * 256 + threadIdx.x;   // 524,288 total
        int lane = i & 31;
        int k16  = (i >> 5) & 63;
        int ms   = (i >> 11) & 1;
        int cb   = (int)(i >> 12);
        int g = lane >> 2, tig = lane & 3;
        int m1 = ms * 16 + g, m2 = m1 + 8;
        int r1 = (m1 & 3) * Hh + cb * 8 + (m1 >> 2);
        int r2 = (m2 & 3) * Hh + cb * 8 + (m2 >> 2);
        int k0 = k16 * 16 + tig * 2;
        uint4 v;
        v.x = pkh2(Wh[(size_t)r1 * Hh + k0],     Wh[(size_t)r1 * Hh + k0 + 1]);
        v.y = pkh2(Wh[(size_t)r2 * Hh + k0],     Wh[(size_t)r2 * Hh + k0 + 1]);
        v.z = pkh2(Wh[(size_t)r1 * Hh + k0 + 8], Wh[(size_t)r1 * Hh + k0 + 9]);
        v.w = pkh2(Wh[(size_t)r2 * Hh + k0 + 8], Wh[(size_t)r2 * Hh + k0 + 9]);
        d_Afh[i] = v;
    } else if (blk < 2560) {
        // Wx fp16 A frag: uint4 i = ((gb*8+ws)*16 + k16)*32 + lane
        size_t i = (size_t)(blk - 2048) * 256 + threadIdx.x;  // 131,072 total
        int lane = i & 31;
        int k16  = (i >> 5) & 15;
        int ws   = (i >> 9) & 7;
        int gb   = (int)(i >> 12);
        int g = lane >> 2, tig = lane & 3;
        int m1 = gb * 128 + ws * 16 + g, m2 = m1 + 8;
        int r1 = (m1 & 3) * Hh + (m1 >> 2);
        int r2 = (m2 & 3) * Hh + (m2 >> 2);
        int k0 = k16 * 16 + tig * 2;
        uint4 v;
        v.x = pkh2(Wx[(size_t)r1 * Dd + k0],     Wx[(size_t)r1 * Dd + k0 + 1]);
        v.y = pkh2(Wx[(size_t)r2 * Dd + k0],     Wx[(size_t)r2 * Dd + k0 + 1]);
        v.z = pkh2(Wx[(size_t)r1 * Dd + k0 + 8], Wx[(size_t)r1 * Dd + k0 + 9]);
        v.w = pkh2(Wx[(size_t)r2 * Dd + k0 + 8], Wx[(size_t)r2 * Dd + k0 + 9]);
        d_Axfh[i] = v;
    } else {
        size_t i = (size_t)(blk - 2560) * 256 + threadIdx.x;
        int lane = i & 31;
        int k8   = (i >> 5) & 127;
        int s    = (int)(i >> 12);
        int g = lane >> 2, tig = lane & 3;
        int d1 = s * 16 + g, d2 = d1 + 8;
        int k0 = k8 * 8;
        float4 v;
        v.x = __uint_as_float(tf32r(Wo[(size_t)d1 * Hh + k0 + tig]));
        v.y = __uint_as_float(tf32r(Wo[(size_t)d2 * Hh + k0 + tig]));
        v.z = __uint_as_float(tf32r(Wo[(size_t)d1 * Hh + k0 + tig + 4]));
        v.w = __uint_as_float(tf32r(Wo[(size_t)d2 * Hh + k0 + tig + 4]));
        ((float4*)d_Wof)[i] = v;
    }
}

// ---------------- GEMM 1 (fp16 mma): xg[t][m][b] = inputs . Wx^T + bx + bh ------
// Grid (32, 4) x 256 thr.  CTA: 128 gate-cols x 64 batch, K=256, TWO t per pass.
// Inputs staged as fp16 [b][k], row = 256 halfs, PITCH 264 halfs (132 words,
// 132 mod 32 = 4 -> B-frag banks 4g+tig, conflict-free).
#define XPH 264
__global__ void __launch_bounds__(256) gemm_xg_mma(
    const float* __restrict__ inp, const float* __restrict__ bx,
    const float* __restrict__ bh)
{
    extern __shared__ __align__(16) unsigned short hsmx[];   // 2 * 64 * XPH halfs
    const int tid = threadIdx.x, w = tid >> 5, lane = tid & 31;
    const int g = lane >> 2, tig = lane & 3;
    const int gb = blockIdx.x;
    const int m1 = gb * 128 + w * 16 + g, m2 = m1 + 8;
    const int r1 = (m1 & 3) * Hh + (m1 >> 2), r2 = (m2 & 3) * Hh + (m2 >> 2);
    const float bias1 = bx[r1] + bh[r1];
    const float bias2 = bx[r2] + bh[r2];
    const uint4* Af = d_Axfh + ((size_t)(gb * 8 + w) * 16) * 32 + lane;
    const int brow = w * 8 + (lane >> 2);
    const int bq = lane & 3;

    for (int t0 = blockIdx.y * 2; t0 < Tt; t0 += 8) {
        // load two input t-slices -> smem fp16 [b][k]
#pragma unroll
        for (int sl = 0; sl < 2; sl++) {
            const float4* src = (const float4*)(inp + ((size_t)brow * Tt + t0 + sl) * Dd);
            unsigned short* dst = hsmx + sl * 64 * XPH + brow * XPH;
#pragma unroll
            for (int i2 = 0; i2 < 16; i2++) {
                float4 v = __ldg(&src[i2 * 4 + bq]);
                uint2 p;
                p.x = pkh2(v.x, v.y);
                p.y = pkh2(v.z, v.w);
                *(uint2*)&dst[(i2 * 4 + bq) * 4] = p;
            }
        }
        __syncthreads();

        float acc[2][8][4];
#pragma unroll
        for (int sl = 0; sl < 2; sl++)
#pragma unroll
            for (int nb = 0; nb < 8; nb++)
#pragma unroll
                for (int q = 0; q < 4; q++) acc[sl][nb][q] = 0.f;

#pragma unroll 4
        for (int k16 = 0; k16 < 16; k16++) {
            uint4 a4 = __ldg(&Af[k16 * 32]);
            const int k0 = k16 * 16;
#pragma unroll
            for (int nb = 0; nb < 8; nb++) {
#pragma unroll
                for (int sl = 0; sl < 2; sl++) {
                    const unsigned short* bp =
                        hsmx + sl * 64 * XPH + (nb * 8 + g) * XPH + k0 + tig * 2;
                    unsigned b0 = *(const unsigned*)bp;
                    unsigned b1 = *(const unsigned*)(bp + 8);
                    MMA_F16(acc[sl][nb], a4.x, a4.y, a4.z, a4.w, b0, b1);
                }
            }
        }
#pragma unroll
        for (int sl = 0; sl < 2; sl++) {
            int t = t0 + sl;
#pragma unroll
            for (int nb = 0; nb < 8; nb++) {
                *(float2*)&d_xg[((size_t)t * Gg + m1) * 64 + nb * 8 + tig * 2] =
                    make_float2(acc[sl][nb][0] + bias1, acc[sl][nb][1] + bias1);
                *(float2*)&d_xg[((size_t)t * Gg + m2) * 64 + nb * 8 + tig * 2] =
                    make_float2(acc[sl][nb][2] + bias2, acc[sl][nb][3] + bias2);
            }
        }
        __syncthreads();
    }
}

// ---------------- persistent LSTM recurrence (fp16 mma, full-h staging) ---------
// 128 CTAs x 512 thr (16 warps).  CTA owns 32 gate-cols, N=64, K=1024.
// Per step: stage ENTIRE h (512 half2-rows x 64 words, pitch 72, 144 KB) with
// ONE sync, then each warp streams its 32 k16 MMAs with no further syncs.
// Warp w: kh = w>>3 (k-half), ms = w&1 (m-strip), n0 = ((w>>1)&3)*16.
// Two D buffers summed in the pointwise.  Barrier is SPLIT: arrive right after
// the h store; d_hsJ store + xg prefetch ride between arrive and wait.
#define HP2 72
#define HS_FULL (512 * HP2)                  // unsigned words (144 KB)
#define DS_P 68
#define DS_SZ  (2 * 32 * DS_P)               // floats
__global__ void __launch_bounds__(512, 1) lstm_mma()
{
    extern __shared__ __align__(16) unsigned smem_u[];
    unsigned* hs  = smem_u;                          // [512][HP2]
    float*    Ds  = (float*)(smem_u + HS_FULL);      // [kh][32*DS_P]
    float*    hnS = Ds + DS_SZ;                      // [8][64]

    const int tid  = threadIdx.x;
    const int cta  = blockIdx.x;
    const int w    = tid >> 5, lane = tid & 31;
    const int g    = lane >> 2, tig = lane & 3;
    const int kh   = w >> 3;
    const int ms   = w & 1;
    const int n0   = ((w >> 1) & 3) * 16;
    const int pb   = tid & 63;           // pointwise batch
    const int jl   = tid >> 6;           // pointwise local j (0..7)
    const uint4* Af = d_Afh + ((size_t)(cta * 2 + ms) * 64 + kh * 32) * 32 + lane;
    float cs = 0.f;

    // prefetch xg for t = 0
    float xg0[4];
#pragma unroll
    for (int q = 0; q < 4; q++)
        xg0[q] = d_xg[(((size_t)0 * Hh + cta * 8 + jl) * 4 + q) * Bb + pb];

    for (int t = 0; t < Tt; t++) {
        const unsigned* hcur = d_h2h + (size_t)(t & 1) * (512 * Bb);
        unsigned*       hnxt = d_h2h + (size_t)((t + 1) & 1) * (512 * Bb);

        // ---- stage full h: 8192 uint4, 512 threads x 16, two MLP-8 batches ----
        {
            uint4 st[8];
#pragma unroll
            for (int p = 0; p < 8; p++)
                st[p] = __ldcg((const uint4*)hcur + p * 512 + tid);
#pragma unroll
            for (int p = 0; p < 8; p++) {
                int idx = p * 512 + tid;
                *(uint4*)&hs[(idx >> 4) * HP2 + (idx & 15) * 4] = st[p];
            }
#pragma unroll
            for (int p = 0; p < 8; p++)
                st[p] = __ldcg((const uint4*)hcur + (p + 8) * 512 + tid);
#pragma unroll
            for (int p = 0; p < 8; p++) {
                int idx = (p + 8) * 512 + tid;
                *(uint4*)&hs[(idx >> 4) * HP2 + (idx & 15) * 4] = st[p];
            }
        }
        __syncthreads();

        // ---- 32 k16 MMAs per warp, no syncs ----
        float acc0[4] = {0.f, 0.f, 0.f, 0.f};
        float acc1[4] = {0.f, 0.f, 0.f, 0.f};
#pragma unroll 8
        for (int kk = 0; kk < 32; kk++) {
            uint4 a4 = __ldg(&Af[kk * 32]);
            const int rb = (kh * 32 + kk) * 8;
            unsigned b0 = hs[(rb + tig) * HP2 + n0 + g];
            unsigned b1 = hs[(rb + tig + 4) * HP2 + n0 + g];
            unsigned b2 = hs[(rb + tig) * HP2 + n0 + 8 + g];
            unsigned b3 = hs[(rb + tig + 4) * HP2 + n0 + 8 + g];
            MMA_F16(acc0, a4.x, a4.y, a4.z, a4.w, b0, b1);
            MMA_F16(acc1, a4.x, a4.y, a4.z, a4.w, b2, b3);
        }

        // D fragments -> per-half smem buffer
        {
            float* D = Ds + kh * (32 * DS_P);
            int r1 = ms * 16 + g, r2 = r1 + 8;
            *(float2*)&D[r1 * DS_P + n0 + tig * 2]     = make_float2(acc0[0], acc0[1]);
            *(float2*)&D[r2 * DS_P + n0 + tig * 2]     = make_float2(acc0[2], acc0[3]);
            *(float2*)&D[r1 * DS_P + n0 + 8 + tig * 2] = make_float2(acc1[0], acc1[1]);
            *(float2*)&D[r2 * DS_P + n0 + 8 + tig * 2] = make_float2(acc1[2], acc1[3]);
        }
        __syncthreads();

        // pointwise: one (jl, pb) per thread; sum the two k-half D buffers.
        // MUFU-based sigmoid/tanh (short serial chain).
        float hn;
        {
            float gi = Ds[(jl * 4 + 0) * DS_P + pb] + Ds[DS_SZ / 2 + (jl * 4 + 0) * DS_P + pb] + xg0[0];
            float gf = Ds[(jl * 4 + 1) * DS_P + pb] + Ds[DS_SZ / 2 + (jl * 4 + 1) * DS_P + pb] + xg0[1];
            float gg = Ds[(jl * 4 + 2) * DS_P + pb] + Ds[DS_SZ / 2 + (jl * 4 + 2) * DS_P + pb] + xg0[2];
            float go = Ds[(jl * 4 + 3) * DS_P + pb] + Ds[DS_SZ / 2 + (jl * 4 + 3) * DS_P + pb] + xg0[3];
            float si = sigm(gi), sf = sigm(gf), sg = sigm(gg), so = sigm(go);
            float cn = cs * sf + si * sg;        // NOTE: sigmoid cell gate (per ref)
            cs = cn;
            hn = so * tanh_fast(cn);
            hnS[jl * 64 + pb] = hn;
        }
        __syncthreads();
        if (tid < 256) {
            int jp = tid >> 6, b = tid & 63;
            __stcg(&hnxt[(cta * 4 + jp) * 64 + b],
                   pkh2(hnS[(2 * jp) * 64 + b], hnS[(2 * jp + 1) * 64 + b]));
        }
        __syncthreads();

        // ---- split barrier: arrive, do lazy work, wait ----
        if (tid == 0)
            asm volatile("red.release.gpu.global.add.u32 [%0], 1;"
                         :: "l"(&d_bcount) : "memory");
        d_hsJ[((size_t)(cta * 8 + jl) * Tt + t) * 64 + pb] = hn;
        if (t + 1 < Tt) {
#pragma unroll
            for (int q = 0; q < 4; q++)
                xg0[q] = d_xg[(((size_t)(t + 1) * Hh + cta * 8 + jl) * 4 + q) * Bb + pb];
        }
        if (tid == 0) {
            unsigned target = (unsigned)NCTA * (t + 1);
            unsigned c;
            do {
                asm volatile("ld.acquire.gpu.global.u32 %0, [%1];"
                             : "=r"(c) : "l"(&d_bcount) : "memory");
            } while (c < target);
        }
        __syncthreads();
    }
}

// ---------------- GEMM 3 (tf32 mma): outT[d][m'] = Wout . hs --------------------
#define HS_P 72
__global__ void __launch_bounds__(256) gemm_out_mma()
{
    __shared__ __align__(16) float hsm[2][64 * HS_P];
    const int tid = threadIdx.x, w = tid >> 5, lane = tid & 31;
    const int g = lane >> 2, tig = lane & 3;
    const int t = blockIdx.x;
    const int lk = tid >> 4, lf = tid & 15;
    const float4* Af1 = (const float4*)d_Wof + (size_t)w * 128 * 32 + lane;
    const float4* Af2 = (const float4*)d_Wof + (size_t)(w + 8) * 128 * 32 + lane;

    float acc[2][8][4];
#pragma unroll
    for (int sh = 0; sh < 2; sh++)
#pragma unroll
        for (int nbq = 0; nbq < 8; nbq++)
#pragma unroll
            for (int q = 0; q < 4; q++) acc[sh][nbq][q] = 0.f;

    float4 st[4];
#pragma unroll
    for (int p = 0; p < 4; p++) {
        int k = p * 16 + lk;
        st[p] = __ldcg((const float4*)&d_hsJ[((size_t)k * Tt + t) * 64 + lf * 4]);
    }

#pragma unroll 1
    for (int ch = 0; ch < 16; ch++) {
        const int buf = ch & 1;
#pragma unroll
        for (int p = 0; p < 4; p++)
            *(float4*)&hsm[buf][(p * 16 + lk) * HS_P + lf * 4] = st[p];
        __syncthreads();
        if (ch < 15) {
#pragma unroll
            for (int p = 0; p < 4; p++) {
                int k = (ch + 1) * 64 + p * 16 + lk;
                st[p] = __ldcg((const float4*)&d_hsJ[((size_t)k * Tt + t) * 64 + lf * 4]);
            }
        }
#pragma unroll
        for (int k8 = 0; k8 < 8; k8++) {
            const int kg = ch * 8 + k8;
            const int kl = k8 * 8;
            float4 af1 = __ldg(&Af1[kg * 32]);
            float4 af2 = __ldg(&Af2[kg * 32]);
#pragma unroll
            for (int nbq = 0; nbq < 8; nbq++) {
                unsigned b0 = tf32r(hsm[buf][(kl + tig) * HS_P + nbq * 8 + g]);
                unsigned b1 = tf32r(hsm[buf][(kl + tig + 4) * HS_P + nbq * 8 + g]);
                MMA_TF32(acc[0][nbq], __float_as_uint(af1.x), __float_as_uint(af1.y),
                         __float_as_uint(af1.z), __float_as_uint(af1.w), b0, b1);
                MMA_TF32(acc[1][nbq], __float_as_uint(af2.x), __float_as_uint(af2.y),
                         __float_as_uint(af2.z), __float_as_uint(af2.w), b0, b1);
            }
        }
        __syncthreads();
    }

#pragma unroll
    for (int sh = 0; sh < 2; sh++) {
        int dbase = (sh ? (w + 8) : w) * 16;
        int d1 = dbase + g, d2 = d1 + 8;
#pragma unroll
        for (int nbq = 0; nbq < 8; nbq++) {
            int bcol = nbq * 8 + tig * 2;
            *(float2*)&d_outT[(size_t)d1 * Mm + t * 64 + bcol] =
                make_float2(acc[sh][nbq][0], acc[sh][nbq][1]);
            *(float2*)&d_outT[(size_t)d2 * Mm + t * 64 + bcol] =
                make_float2(acc[sh][nbq][2], acc[sh][nbq][3]);
        }
    }
}

// ---------------- hidden = tanh(hs), [j][m'] -> [b][t][j] ----------------------
__global__ void tanhT_k(float* __restrict__ outH)
{
    __shared__ float tile[32][33];
    int m0 = blockIdx.x * 32;
    int j0 = blockIdx.y * 32;
    int tx = threadIdx.x, ty = threadIdx.y;
#pragma unroll
    for (int i = 0; i < 32; i += 8)
        tile[ty + i][tx] = d_hsJ[(size_t)(j0 + ty + i) * Mm + m0 + tx];
    __syncthreads();
    int t0 = m0 >> 6;
    int bbase = m0 & 63;
#pragma unroll
    for (int i = 0; i < 32; i += 8) {
        int mp = ty + i;
        int b = bbase + mp;
        outH[((size_t)b * Tt + t0) * Hh + j0 + tx] = tanh_ap(tile[tx][mp]);
    }
}

// ---------------- out = outT^T + bias: [d][m'] -> [b][t][d] ---------------------
__global__ void outT_k(const float* __restrict__ bo, float* __restrict__ outp)
{
    __shared__ float tile[32][33];
    int m0 = blockIdx.x * 32;
    int d0 = blockIdx.y * 32;
    int tx = threadIdx.x, ty = threadIdx.y;
#pragma unroll
    for (int i = 0; i < 32; i += 8)
        tile[ty + i][tx] = d_outT[(size_t)(d0 + ty + i) * Mm + m0 + tx];
    __syncthreads();
    int t0 = m0 >> 6;
    int bbase = m0 & 63;
    float bv = bo[d0 + tx];
#pragma unroll
    for (int i = 0; i < 32; i += 8) {
        int b = bbase + ty + i;
        outp[((size_t)b * Tt + t0) * Dd + d0 + tx] = tile[tx][ty + i] + bv;
    }
}

// ---------------- launch --------------------------------------------------------
extern "C" void kernel_launch(void* const* d_in, const int* in_sizes, int n_in,
                              void* d_out, int out_size)
{
    (void)in_sizes; (void)n_in; (void)out_size;
    const float* inp = (const float*)d_in[0];
    const float* Wx  = (const float*)d_in[1];
    const float* bx  = (const float*)d_in[2];
    const float* Wh  = (const float*)d_in[3];
    const float* bh  = (const float*)d_in[4];
    const float* Wo  = (const float*)d_in[5];
    const float* bo  = (const float*)d_in[6];
    float* out = (float*)d_out;
    float* outHidden = out + (size_t)Bb * Tt * Dd;

    const int xg_smem = 2 * 64 * XPH * sizeof(unsigned short);  // 67,584 B
    cudaFuncSetAttribute(gemm_xg_mma,
                         cudaFuncAttributeMaxDynamicSharedMemorySize, xg_smem);
    const int lstm_smem = (HS_FULL + DS_SZ + 512) * 4;          // ~166.9 KB
    cudaFuncSetAttribute(lstm_mma,
                         cudaFuncAttributeMaxDynamicSharedMemorySize, lstm_smem);

    init_k<<<256, 256>>>();                                  // #1 (also resets barrier)
    pack_all<<<2816, 256>>>(Wh, Wx, Wo);                     // #2
    gemm_xg_mma<<<dim3(32, 4), 256, xg_smem>>>(inp, bx, bh); // #3
    lstm_mma<<<NCTA, 512, lstm_smem>>>();                    // #4 -> profiled
    gemm_out_mma<<<Tt, 256>>>();                             // #5
    tanhT_k<<<dim3(Mm / 32, Hh / 32), dim3(32, 8)>>>(outHidden);
    outT_k<<<dim3(Mm / 32, Dd / 32), dim3(32, 8)>>>(bo, out);
}

// round 15
// speedup vs baseline: 2.8743x; 1.0389x over previous
#include <cuda_runtime.h>
#include <cuda_fp16.h>
#include <math.h>

// Problem dims
#define Bb   64
#define Tt   512
#define Dd   256
#define Hh   1024
#define Gg   4096          // 4*H
#define Mm   32768         // B*T
#define NCTA 128

// ---------------- scratch (__device__ globals; no dynamic allocation) ----------
__device__ float d_xg[(size_t)Tt * Gg * Bb];      // [t][m=j*4+g][b]   512 MB
__device__ uint4 d_Afh[(size_t)NCTA * 2 * 64 * 32];   // Wh fp16 A-frags, 8 MB
__device__ uint4 d_Axfh[(size_t)32 * 8 * 16 * 32];    // Wx fp16 A-frags, 2 MB
__device__ float d_Wof[(size_t)Dd * Hh];          // Wout tf32 A-fragments, 1 MB
__device__ float d_hsJ[(size_t)Hh * Mm];          // [j][m'] , m'=t*64+b   128 MB
__device__ float d_outT[(size_t)Dd * Mm];         // out head, [d][m']     32 MB
__device__ unsigned d_h2h[2 * 512 * Bb];          // double-buffered h, half2 [buf][k/2][b]
__device__ unsigned d_bcount;

__device__ __forceinline__ unsigned tf32r(float x)
{
    unsigned u;
    asm("cvt.rna.tf32.f32 %0, %1;" : "=r"(u) : "f"(x));
    return u;
}
__device__ __forceinline__ float tanh_ap(float x)
{
    float y;
    asm("tanh.approx.f32 %0, %1;" : "=f"(y) : "f"(x));
    return y;
}
__device__ __forceinline__ unsigned pkh2(float lo, float hi)
{
    __half2 h = __floats2half2_rn(lo, hi);
    return *(unsigned*)&h;
}
// fast (MUFU) sigmoid / tanh: rel err ~2^-21, negligible vs fp16-h noise
__device__ __forceinline__ float sigm(float x)
{
    return __fdividef(1.f, 1.f + __expf(-x));
}
__device__ __forceinline__ float tanh_fast(float x)
{
    return __fdividef(2.f, 1.f + __expf(-2.f * x)) - 1.f;
}

// tf32 mma: D(m16n8) += A(m16k8) * B(k8n8)
#define MMA_TF32(d, a0, a1, a2, a3, b0, b1)                                     \
    asm volatile("mma.sync.aligned.m16n8k8.row.col.f32.tf32.tf32.f32 "          \
                 "{%0,%1,%2,%3}, {%4,%5,%6,%7}, {%8,%9}, {%0,%1,%2,%3};"        \
                 : "+f"(d[0]), "+f"(d[1]), "+f"(d[2]), "+f"(d[3])               \
                 : "r"(a0), "r"(a1), "r"(a2), "r"(a3), "r"(b0), "r"(b1))

// fp16 mma: D(m16n8) += A(m16k16) * B(k16n8), fp32 accum
#define MMA_F16(d, a0, a1, a2, a3, b0, b1)                                      \
    asm volatile("mma.sync.aligned.m16n8k16.row.col.f32.f16.f16.f32 "           \
                 "{%0,%1,%2,%3}, {%4,%5,%6,%7}, {%8,%9}, {%0,%1,%2,%3};"        \
                 : "+f"(d[0]), "+f"(d[1]), "+f"(d[2]), "+f"(d[3])               \
                 : "r"(a0), "r"(a1), "r"(a2), "r"(a3), "r"(b0), "r"(b1))

// ---------------- init: zero h state, reset barrier -----------------------------
__global__ void init_k()
{
    int i = blockIdx.x * blockDim.x + threadIdx.x;
    if (i < 2 * 512 * Bb) d_h2h[i] = 0u;
    if (i == 0) d_bcount = 0u;
}

// ---------------- combined weight-fragment packing ------------------------------
// blocks [0,2048): Wh fp16   [2048,2560): Wx fp16   [2560,2816): Wout tf32
__global__ void pack_all(const float* __restrict__ Wh, const float* __restrict__ Wx,
                         const float* __restrict__ Wo)
{
    int blk = blockIdx.x;
    if (blk < 2048) {
        // Wh fp16 A frag: uint4 i = ((cb*2+ms)*64 + k16)*32 + lane
        size_t i = (size_t)blk * 256 + threadIdx.x;   // 524,288 total
        int lane = i & 31;
        int k16  = (i >> 5) & 63;
        int ms   = (i >> 11) & 1;
        int cb   = (int)(i >> 12);
        int g = lane >> 2, tig = lane & 3;
        int m1 = ms * 16 + g, m2 = m1 + 8;
        int r1 = (m1 & 3) * Hh + cb * 8 + (m1 >> 2);
        int r2 = (m2 & 3) * Hh + cb * 8 + (m2 >> 2);
        int k0 = k16 * 16 + tig * 2;
        uint4 v;
        v.x = pkh2(Wh[(size_t)r1 * Hh + k0],     Wh[(size_t)r1 * Hh + k0 + 1]);
        v.y = pkh2(Wh[(size_t)r2 * Hh + k0],     Wh[(size_t)r2 * Hh + k0 + 1]);
        v.z = pkh2(Wh[(size_t)r1 * Hh + k0 + 8], Wh[(size_t)r1 * Hh + k0 + 9]);
        v.w = pkh2(Wh[(size_t)r2 * Hh + k0 + 8], Wh[(size_t)r2 * Hh + k0 + 9]);
        d_Afh[i] = v;
    } else if (blk < 2560) {
        // Wx fp16 A frag: uint4 i = ((gb*8+ws)*16 + k16)*32 + lane
        size_t i = (size_t)(blk - 2048) * 256 + threadIdx.x;  // 131,072 total
        int lane = i & 31;
        int k16  = (i >> 5) & 15;
        int ws   = (i >> 9) & 7;
        int gb   = (int)(i >> 12);
        int g = lane >> 2, tig = lane & 3;
        int m1 = gb * 128 + ws * 16 + g, m2 = m1 + 8;
        int r1 = (m1 & 3) * Hh + (m1 >> 2);
        int r2 = (m2 & 3) * Hh + (m2 >> 2);
        int k0 = k16 * 16 + tig * 2;
        uint4 v;
        v.x = pkh2(Wx[(size_t)r1 * Dd + k0],     Wx[(size_t)r1 * Dd + k0 + 1]);
        v.y = pkh2(Wx[(size_t)r2 * Dd + k0],     Wx[(size_t)r2 * Dd + k0 + 1]);
        v.z = pkh2(Wx[(size_t)r1 * Dd + k0 + 8], Wx[(size_t)r1 * Dd + k0 + 9]);
        v.w = pkh2(Wx[(size_t)r2 * Dd + k0 + 8], Wx[(size_t)r2 * Dd + k0 + 9]);
        d_Axfh[i] = v;
    } else {
        size_t i = (size_t)(blk - 2560) * 256 + threadIdx.x;
        int lane = i & 31;
        int k8   = (i >> 5) & 127;
        int s    = (int)(i >> 12);
        int g = lane >> 2, tig = lane & 3;
        int d1 = s * 16 + g, d2 = d1 + 8;
        int k0 = k8 * 8;
        float4 v;
        v.x = __uint_as_float(tf32r(Wo[(size_t)d1 * Hh + k0 + tig]));
        v.y = __uint_as_float(tf32r(Wo[(size_t)d2 * Hh + k0 + tig]));
        v.z = __uint_as_float(tf32r(Wo[(size_t)d1 * Hh + k0 + tig + 4]));
        v.w = __uint_as_float(tf32r(Wo[(size_t)d2 * Hh + k0 + tig + 4]));
        ((float4*)d_Wof)[i] = v;
    }
}

// ---------------- GEMM 1 (fp16 mma): xg[t][m][b] = inputs . Wx^T + bx + bh ------
// Inputs staged as fp16 [b][k], row = 256 halfs, PITCH 264 halfs.
#define XPH 264
__global__ void __launch_bounds__(256) gemm_xg_mma(
    const float* __restrict__ inp, const float* __restrict__ bx,
    const float* __restrict__ bh)
{
    extern __shared__ __align__(16) unsigned short hsmx[];   // 2 * 64 * XPH halfs
    const int tid = threadIdx.x, w = tid >> 5, lane = tid & 31;
    const int g = lane >> 2, tig = lane & 3;
    const int gb = blockIdx.x;
    const int m1 = gb * 128 + w * 16 + g, m2 = m1 + 8;
    const int r1 = (m1 & 3) * Hh + (m1 >> 2), r2 = (m2 & 3) * Hh + (m2 >> 2);
    const float bias1 = bx[r1] + bh[r1];
    const float bias2 = bx[r2] + bh[r2];
    const uint4* Af = d_Axfh + ((size_t)(gb * 8 + w) * 16) * 32 + lane;
    const int brow = w * 8 + (lane >> 2);
    const int bq = lane & 3;

    for (int t0 = blockIdx.y * 2; t0 < Tt; t0 += 8) {
#pragma unroll
        for (int sl = 0; sl < 2; sl++) {
            const float4* src = (const float4*)(inp + ((size_t)brow * Tt + t0 + sl) * Dd);
            unsigned short* dst = hsmx + sl * 64 * XPH + brow * XPH;
#pragma unroll
            for (int i2 = 0; i2 < 16; i2++) {
                float4 v = __ldg(&src[i2 * 4 + bq]);
                uint2 p;
                p.x = pkh2(v.x, v.y);
                p.y = pkh2(v.z, v.w);
                *(uint2*)&dst[(i2 * 4 + bq) * 4] = p;
            }
        }
        __syncthreads();

        float acc[2][8][4];
#pragma unroll
        for (int sl = 0; sl < 2; sl++)
#pragma unroll
            for (int nb = 0; nb < 8; nb++)
#pragma unroll
                for (int q = 0; q < 4; q++) acc[sl][nb][q] = 0.f;

#pragma unroll 4
        for (int k16 = 0; k16 < 16; k16++) {
            uint4 a4 = __ldg(&Af[k16 * 32]);
            const int k0 = k16 * 16;
#pragma unroll
            for (int nb = 0; nb < 8; nb++) {
#pragma unroll
                for (int sl = 0; sl < 2; sl++) {
                    const unsigned short* bp =
                        hsmx + sl * 64 * XPH + (nb * 8 + g) * XPH + k0 + tig * 2;
                    unsigned b0 = *(const unsigned*)bp;
                    unsigned b1 = *(const unsigned*)(bp + 8);
                    MMA_F16(acc[sl][nb], a4.x, a4.y, a4.z, a4.w, b0, b1);
                }
            }
        }
#pragma unroll
        for (int sl = 0; sl < 2; sl++) {
            int t = t0 + sl;
#pragma unroll
            for (int nb = 0; nb < 8; nb++) {
                *(float2*)&d_xg[((size_t)t * Gg + m1) * 64 + nb * 8 + tig * 2] =
                    make_float2(acc[sl][nb][0] + bias1, acc[sl][nb][1] + bias1);
                *(float2*)&d_xg[((size_t)t * Gg + m2) * 64 + nb * 8 + tig * 2] =
                    make_float2(acc[sl][nb][2] + bias2, acc[sl][nb][3] + bias2);
            }
        }
        __syncthreads();
    }
}

// ---------------- persistent LSTM recurrence (fp16 mma, cp.async, kq-split) -----
// 128 CTAs x 512 thr (16 warps).  CTA owns 32 gate-cols, N=64, K=1024.
// Per step: cp.async the ENTIRE h (512 half2-rows x 64 words, pitch 72, 144 KB),
// one wait+sync, then each warp streams its k-QUARTER with BOTH m-strips (B
// fragments loaded once, 4 MMAs each -> half the B LDS traffic).  Four D
// buffers (one per quarter) summed in the pointwise.  Split grid barrier.
#define HP2 72
#define HS_FULL (512 * HP2)                  // unsigned words (144 KB)
#define DS_P 68
#define DS_Q (32 * DS_P)                     // floats per quarter buffer
#define DS_SZ (4 * DS_Q)                     // floats
__global__ void __launch_bounds__(512, 1) lstm_mma()
{
    extern __shared__ __align__(16) unsigned smem_u[];
    unsigned* hs  = smem_u;                          // [512][HP2]
    float*    Ds  = (float*)(smem_u + HS_FULL);      // [kq][32*DS_P]
    float*    hnS = Ds + DS_SZ;                      // [8][64]

    const int tid  = threadIdx.x;
    const int cta  = blockIdx.x;
    const int w    = tid >> 5, lane = tid & 31;
    const int g    = lane >> 2, tig = lane & 3;
    const int kq   = w >> 2;             // k-quarter 0..3
    const int n0   = (w & 3) * 16;       // n-group
    const int pb   = tid & 63;           // pointwise batch
    const int jl   = tid >> 6;           // pointwise local j (0..7)
    const uint4* Af0 = d_Afh + ((size_t)(cta * 2 + 0) * 64) * 32 + lane;
    const uint4* Af1 = d_Afh + ((size_t)(cta * 2 + 1) * 64) * 32 + lane;
    const unsigned hs_base = (unsigned)__cvta_generic_to_shared(hs);
    float cs = 0.f;

    // prefetch xg for t = 0
    float xg0[4];
#pragma unroll
    for (int q = 0; q < 4; q++)
        xg0[q] = d_xg[(((size_t)0 * Hh + cta * 8 + jl) * 4 + q) * Bb + pb];

    for (int t = 0; t < Tt; t++) {
        const unsigned* hcur = d_h2h + (size_t)(t & 1) * (512 * Bb);
        unsigned*       hnxt = d_h2h + (size_t)((t + 1) & 1) * (512 * Bb);

        // ---- stage full h via cp.async: 8192 uint4, 16 per thread ----
#pragma unroll
        for (int p = 0; p < 16; p++) {
            int idx = p * 512 + tid;
            unsigned dst = hs_base + ((idx >> 4) * HP2 + (idx & 15) * 4) * 4;
            asm volatile("cp.async.cg.shared.global [%0], [%1], 16;"
                         :: "r"(dst), "l"((const uint4*)hcur + idx) : "memory");
        }
        asm volatile("cp.async.commit_group;" ::: "memory");
        asm volatile("cp.async.wait_group 0;" ::: "memory");
        __syncthreads();

        // ---- 16 k16 per warp (its quarter), both m-strips, B loaded once ----
        float accA0[4] = {0.f, 0.f, 0.f, 0.f};
        float accA1[4] = {0.f, 0.f, 0.f, 0.f};
        float accB0[4] = {0.f, 0.f, 0.f, 0.f};
        float accB1[4] = {0.f, 0.f, 0.f, 0.f};
#pragma unroll 8
        for (int i = 0; i < 16; i++) {
            const int kk = kq * 16 + i;
            uint4 a0 = __ldg(&Af0[kk * 32]);
            uint4 a1 = __ldg(&Af1[kk * 32]);
            const int rb = kk * 8;
            unsigned b0 = hs[(rb + tig) * HP2 + n0 + g];
            unsigned b1 = hs[(rb + tig + 4) * HP2 + n0 + g];
            unsigned b2 = hs[(rb + tig) * HP2 + n0 + 8 + g];
            unsigned b3 = hs[(rb + tig + 4) * HP2 + n0 + 8 + g];
            MMA_F16(accA0, a0.x, a0.y, a0.z, a0.w, b0, b1);
            MMA_F16(accA1, a0.x, a0.y, a0.z, a0.w, b2, b3);
            MMA_F16(accB0, a1.x, a1.y, a1.z, a1.w, b0, b1);
            MMA_F16(accB1, a1.x, a1.y, a1.z, a1.w, b2, b3);
        }

        // D fragments -> per-quarter smem buffer (rows = local m, cols = batch)
        {
            float* D = Ds + kq * DS_Q;
            int r1 = g, r2 = g + 8, r3 = g + 16, r4 = g + 24;
            *(float2*)&D[r1 * DS_P + n0 + tig * 2]     = make_float2(accA0[0], accA0[1]);
            *(float2*)&D[r2 * DS_P + n0 + tig * 2]     = make_float2(accA0[2], accA0[3]);
            *(float2*)&D[r1 * DS_P + n0 + 8 + tig * 2] = make_float2(accA1[0], accA1[1]);
            *(float2*)&D[r2 * DS_P + n0 + 8 + tig * 2] = make_float2(accA1[2], accA1[3]);
            *(float2*)&D[r3 * DS_P + n0 + tig * 2]     = make_float2(accB0[0], accB0[1]);
            *(float2*)&D[r4 * DS_P + n0 + tig * 2]     = make_float2(accB0[2], accB0[3]);
            *(float2*)&D[r3 * DS_P + n0 + 8 + tig * 2] = make_float2(accB1[0], accB1[1]);
            *(float2*)&D[r4 * DS_P + n0 + 8 + tig * 2] = make_float2(accB1[2], accB1[3]);
        }
        __syncthreads();

        // pointwise: one (jl, pb) per thread; sum the FOUR k-quarter D buffers
        float hn;
        {
            float gt[4];
#pragma unroll
            for (int q = 0; q < 4; q++) {
                int off = (jl * 4 + q) * DS_P + pb;
                gt[q] = Ds[off] + Ds[DS_Q + off] + Ds[2 * DS_Q + off]
                      + Ds[3 * DS_Q + off] + xg0[q];
            }
            float si = sigm(gt[0]), sf = sigm(gt[1]);
            float sg = sigm(gt[2]), so = sigm(gt[3]);
            float cn = cs * sf + si * sg;        // NOTE: sigmoid cell gate (per ref)
            cs = cn;
            hn = so * tanh_fast(cn);
            hnS[jl * 64 + pb] = hn;
        }
        __syncthreads();
        if (tid < 256) {
            int jp = tid >> 6, b = tid & 63;
            __stcg(&hnxt[(cta * 4 + jp) * 64 + b],
                   pkh2(hnS[(2 * jp) * 64 + b], hnS[(2 * jp + 1) * 64 + b]));
        }
        __syncthreads();

        // ---- split barrier: arrive, do lazy work, wait ----
        if (tid == 0)
            asm volatile("red.release.gpu.global.add.u32 [%0], 1;"
                         :: "l"(&d_bcount) : "memory");
        d_hsJ[((size_t)(cta * 8 + jl) * Tt + t) * 64 + pb] = hn;
        if (t + 1 < Tt) {
#pragma unroll
            for (int q = 0; q < 4; q++)
                xg0[q] = d_xg[(((size_t)(t + 1) * Hh + cta * 8 + jl) * 4 + q) * Bb + pb];
        }
        if (tid == 0) {
            unsigned target = (unsigned)NCTA * (t + 1);
            unsigned c;
            do {
                asm volatile("ld.acquire.gpu.global.u32 %0, [%1];"
                             : "=r"(c) : "l"(&d_bcount) : "memory");
            } while (c < target);
        }
        __syncthreads();
    }
}

// ---------------- GEMM 3 (tf32 mma): outT[d][m'] = Wout . hs --------------------
#define HS_P 72
__global__ void __launch_bounds__(256) gemm_out_mma()
{
    __shared__ __align__(16) float hsm[2][64 * HS_P];
    const int tid = threadIdx.x, w = tid >> 5, lane = tid & 31;
    const int g = lane >> 2, tig = lane & 3;
    const int t = blockIdx.x;
    const int lk = tid >> 4, lf = tid & 15;
    const float4* Af1 = (const float4*)d_Wof + (size_t)w * 128 * 32 + lane;
    const float4* Af2 = (const float4*)d_Wof + (size_t)(w + 8) * 128 * 32 + lane;

    float acc[2][8][4];
#pragma unroll
    for (int sh = 0; sh < 2; sh++)
#pragma unroll
        for (int nbq = 0; nbq < 8; nbq++)
#pragma unroll
            for (int q = 0; q < 4; q++) acc[sh][nbq][q] = 0.f;

    float4 st[4];
#pragma unroll
    for (int p = 0; p < 4; p++) {
        int k = p * 16 + lk;
        st[p] = __ldcg((const float4*)&d_hsJ[((size_t)k * Tt + t) * 64 + lf * 4]);
    }

#pragma unroll 1
    for (int ch = 0; ch < 16; ch++) {
        const int buf = ch & 1;
#pragma unroll
        for (int p = 0; p < 4; p++)
            *(float4*)&hsm[buf][(p * 16 + lk) * HS_P + lf * 4] = st[p];
        __syncthreads();
        if (ch < 15) {
#pragma unroll
            for (int p = 0; p < 4; p++) {
                int k = (ch + 1) * 64 + p * 16 + lk;
                st[p] = __ldcg((const float4*)&d_hsJ[((size_t)k * Tt + t) * 64 + lf * 4]);
            }
        }
#pragma unroll
        for (int k8 = 0; k8 < 8; k8++) {
            const int kg = ch * 8 + k8;
            const int kl = k8 * 8;
            float4 af1 = __ldg(&Af1[kg * 32]);
            float4 af2 = __ldg(&Af2[kg * 32]);
#pragma unroll
            for (int nbq = 0; nbq < 8; nbq++) {
                unsigned b0 = tf32r(hsm[buf][(kl + tig) * HS_P + nbq * 8 + g]);
                unsigned b1 = tf32r(hsm[buf][(kl + tig + 4) * HS_P + nbq * 8 + g]);
                MMA_TF32(acc[0][nbq], __float_as_uint(af1.x), __float_as_uint(af1.y),
                         __float_as_uint(af1.z), __float_as_uint(af1.w), b0, b1);
                MMA_TF32(acc[1][nbq], __float_as_uint(af2.x), __float_as_uint(af2.y),
                         __float_as_uint(af2.z), __float_as_uint(af2.w), b0, b1);
            }
        }
        __syncthreads();
    }

#pragma unroll
    for (int sh = 0; sh < 2; sh++) {
        int dbase = (sh ? (w + 8) : w) * 16;
        int d1 = dbase + g, d2 = d1 + 8;
#pragma unroll
        for (int nbq = 0; nbq < 8; nbq++) {
            int bcol = nbq * 8 + tig * 2;
            *(float2*)&d_outT[(size_t)d1 * Mm + t * 64 + bcol] =
                make_float2(acc[sh][nbq][0], acc[sh][nbq][1]);
            *(float2*)&d_outT[(size_t)d2 * Mm + t * 64 + bcol] =
                make_float2(acc[sh][nbq][2], acc[sh][nbq][3]);
        }
    }
}

// ---------------- hidden = tanh(hs), [j][m'] -> [b][t][j] ----------------------
__global__ void tanhT_k(float* __restrict__ outH)
{
    __shared__ float tile[32][33];
    int m0 = blockIdx.x * 32;
    int j0 = blockIdx.y * 32;
    int tx = threadIdx.x, ty = threadIdx.y;
#pragma unroll
    for (int i = 0; i < 32; i += 8)
        tile[ty + i][tx] = d_hsJ[(size_t)(j0 + ty + i) * Mm + m0 + tx];
    __syncthreads();
    int t0 = m0 >> 6;
    int bbase = m0 & 63;
#pragma unroll
    for (int i = 0; i < 32; i += 8) {
        int mp = ty + i;
        int b = bbase + mp;
        outH[((size_t)b * Tt + t0) * Hh + j0 + tx] = tanh_ap(tile[tx][mp]);
    }
}

// ---------------- out = outT^T + bias: [d][m'] -> [b][t][d] ---------------------
__global__ void outT_k(const float* __restrict__ bo, float* __restrict__ outp)
{
    __shared__ float tile[32][33];
    int m0 = blockIdx.x * 32;
    int d0 = blockIdx.y * 32;
    int tx = threadIdx.x, ty = threadIdx.y;
#pragma unroll
    for (int i = 0; i < 32; i += 8)
        tile[ty + i][tx] = d_outT[(size_t)(d0 + ty + i) * Mm + m0 + tx];
    __syncthreads();
    int t0 = m0 >> 6;
    int bbase = m0 & 63;
    float bv = bo[d0 + tx];
#pragma unroll
    for (int i = 0; i < 32; i += 8) {
        int b = bbase + ty + i;
        outp[((size_t)b * Tt + t0) * Dd + d0 + tx] = tile[tx][ty + i] + bv;
    }
}

// ---------------- launch --------------------------------------------------------
extern "C" void kernel_launch(void* const* d_in, const int* in_sizes, int n_in,
                              void* d_out, int out_size)
{
    (void)in_sizes; (void)n_in; (void)out_size;
    const float* inp = (const float*)d_in[0];
    const float* Wx  = (const float*)d_in[1];
    const float* bx  = (const float*)d_in[2];
    const float* Wh  = (const float*)d_in[3];
    const float* bh  = (const float*)d_in[4];
    const float* Wo  = (const float*)d_in[5];
    const float* bo  = (const float*)d_in[6];
    float* out = (float*)d_out;
    float* outHidden = out + (size_t)Bb * Tt * Dd;

    const int xg_smem = 2 * 64 * XPH * sizeof(unsigned short);  // 67,584 B
    cudaFuncSetAttribute(gemm_xg_mma,
                         cudaFuncAttributeMaxDynamicSharedMemorySize, xg_smem);
    const int lstm_smem = (HS_FULL + DS_SZ + 512) * 4;          // ~184.3 KB
    cudaFuncSetAttribute(lstm_mma,
                         cudaFuncAttributeMaxDynamicSharedMemorySize, lstm_smem);

    init_k<<<256, 256>>>();                                  // #1 (also resets barrier)
    pack_all<<<2816, 256>>>(Wh, Wx, Wo);                     // #2
    gemm_xg_mma<<<dim3(32, 4), 256, xg_smem>>>(inp, bx, bh); // #3
    lstm_mma<<<NCTA, 512, lstm_smem>>>();                    // #4 -> profiled
    gemm_out_mma<<<Tt, 256>>>();                             // #5
    tanhT_k<<<dim3(Mm / 32, Hh / 32), dim3(32, 8)>>>(outHidden);
    outT_k<<<dim3(Mm / 32, Dd / 32), dim3(32, 8)>>>(bo, out);
}